// round 4
// baseline (speedup 1.0000x reference)
#include <cuda_runtime.h>
#include <math.h>

#define S_LEN 2048
#define BATCH 2
#define TOK   (BATCH * S_LEN)   // 4096
#define HID   2048
#define NH    16
#define NKV   4
#define HD    128
#define QDIM  (NH * HD)         // 2048
#define KVDIM (NKV * HD)        // 512

// ---------------- scratch (static device arrays; no allocs) ----------------
__device__ float g_Q[TOK * QDIM];
__device__ float g_K[TOK * KVDIM];
__device__ float g_V[TOK * KVDIM];
__device__ float g_G1[TOK * NH];
__device__ float g_G2[TOK * NH];
__device__ float g_O[TOK * QDIM];

// ---------------- SGEMM core: 128x128 tile, BK=8, 256 thr, 8x8 microtile ---
// Two-stage shared-memory pipeline + register prefetch: one barrier per slab.
__device__ __forceinline__ void sgemm_tile(
    const float* __restrict__ A, const float* __restrict__ B,
    float* __restrict__ C, int ldc, int K, int N_B,
    int brow, int bcol)
{
    __shared__ float As[2][8][128];
    __shared__ float Bs[2][8][132];   // padded

    const int tid  = threadIdx.x;
    const int aRow = tid >> 1;          // 0..127
    const int aCol = (tid & 1) << 2;    // 0 or 4
    const int bRow = tid >> 5;          // 0..7
    const int bCol = (tid & 31) << 2;   // 0..124
    const int tr   = (tid >> 4) << 3;
    const int tc   = (tid & 15) << 3;

    float acc[8][8];
#pragma unroll
    for (int i = 0; i < 8; i++)
#pragma unroll
        for (int j = 0; j < 8; j++) acc[i][j] = 0.f;

    const float* Aptr = A + (size_t)(brow + aRow) * K + aCol;
    const float* Bptr = B + (size_t)bRow * N_B + bcol + bCol;

    // preload slab 0 into stage 0
    float4 a4 = *(const float4*)(Aptr);
    float4 b4 = *(const float4*)(Bptr);
    As[0][aCol + 0][aRow] = a4.x;
    As[0][aCol + 1][aRow] = a4.y;
    As[0][aCol + 2][aRow] = a4.z;
    As[0][aCol + 3][aRow] = a4.w;
    *(float4*)&Bs[0][bRow][bCol] = b4;
    __syncthreads();

    int cur = 0;
    for (int k0 = 0; k0 < K; k0 += 8) {
        const bool has_next = (k0 + 8 < K);
        if (has_next) {
            a4 = *(const float4*)(Aptr + k0 + 8);
            b4 = *(const float4*)(Bptr + (size_t)(k0 + 8) * N_B);
        }
#pragma unroll
        for (int k = 0; k < 8; k++) {
            float af[8], bf[8];
            *(float4*)&af[0] = *(float4*)&As[cur][k][tr];
            *(float4*)&af[4] = *(float4*)&As[cur][k][tr + 4];
            *(float4*)&bf[0] = *(float4*)&Bs[cur][k][tc];
            *(float4*)&bf[4] = *(float4*)&Bs[cur][k][tc + 4];
#pragma unroll
            for (int i = 0; i < 8; i++)
#pragma unroll
                for (int j = 0; j < 8; j++) acc[i][j] = fmaf(af[i], bf[j], acc[i][j]);
        }
        if (has_next) {
            const int nxt = cur ^ 1;
            As[nxt][aCol + 0][aRow] = a4.x;
            As[nxt][aCol + 1][aRow] = a4.y;
            As[nxt][aCol + 2][aRow] = a4.z;
            As[nxt][aCol + 3][aRow] = a4.w;
            *(float4*)&Bs[nxt][bRow][bCol] = b4;
            cur = nxt;
            __syncthreads();
        }
    }

#pragma unroll
    for (int i = 0; i < 8; i++) {
        float4* cp = (float4*)(C + (size_t)(brow + tr + i) * ldc + bcol + tc);
        cp[0] = make_float4(acc[i][0], acc[i][1], acc[i][2], acc[i][3]);
        cp[1] = make_float4(acc[i][4], acc[i][5], acc[i][6], acc[i][7]);
    }
}

// Plain GEMM: C[M,N] = A[M,K] @ B[K,N]
__global__ __launch_bounds__(256, 2)
void sgemm128(const float* __restrict__ A, const float* __restrict__ B,
              float* __restrict__ C, int M, int N, int K) {
    sgemm_tile(A, B, C, N, K, N, blockIdx.y * 128, blockIdx.x * 128);
}

// Fused QKV projection: logical B = [Wq | Wk | Wv] (2048 x 3072), outputs
// routed to separate scratch buffers. gridDim.x = 24 column tiles.
__global__ __launch_bounds__(256, 2)
void sgemm_qkv(const float* __restrict__ A,
               const float* __restrict__ Wq, const float* __restrict__ Wk,
               const float* __restrict__ Wv,
               float* __restrict__ Q, float* __restrict__ Ko, float* __restrict__ Vo) {
    const int ct = blockIdx.x;   // 0..23
    const float* B;
    float* C;
    int nb, col;
    if (ct < 16)      { B = Wq; C = Q;  nb = QDIM;  col = ct; }
    else if (ct < 20) { B = Wk; C = Ko; nb = KVDIM; col = ct - 16; }
    else              { B = Wv; C = Vo; nb = KVDIM; col = ct - 20; }
    sgemm_tile(A, B, C, nb, HID, nb, blockIdx.y * 128, col * 128);
}

// ---------------- RoPE (in-place on [T, nheads*128] layout) ----------------
__global__ void rope_kernel(float* __restrict__ X, const int* __restrict__ pos_ids,
                            int nheads) {
    const int total = TOK * nheads * 64;
    for (int idx = blockIdx.x * blockDim.x + threadIdx.x; idx < total;
         idx += gridDim.x * blockDim.x) {
        const int d    = idx & 63;
        const int rest = idx >> 6;
        const int h    = rest % nheads;
        const int t    = rest / nheads;
        const int s    = t & (S_LEN - 1);
        const int pos  = pos_ids[s];
        // inv_freq = 10000^(-d/64); angle in double + reduce mod 2pi
        const double invf = exp(-(double)d * (9.210340371976184 / 64.0));
        const double ang  = fmod((double)pos * invf, 6.283185307179586);
        float sn, cs;
        sincosf((float)ang, &sn, &cs);
        float* base = X + (size_t)t * (nheads * HD) + h * HD;
        const float x0 = base[d];
        const float x1 = base[d + 64];
        base[d]      = x0 * cs - x1 * sn;
        base[d + 64] = x1 * cs + x0 * sn;
    }
}

// ---------------- gates: sigmoid(X @ Wg + bg), [T,16] each -----------------
__global__ void gates_kernel(const float* __restrict__ X,
                             const float* __restrict__ Wg1, const float* __restrict__ bg1,
                             const float* __restrict__ Wg2, const float* __restrict__ bg2,
                             float* __restrict__ G1, float* __restrict__ G2) {
    const int t    = blockIdx.x;
    const int warp = threadIdx.x >> 5;   // 0..7
    const int lane = threadIdx.x & 31;
    const float* x = X + (size_t)t * HID;
    float s0 = 0.f, s1 = 0.f, s2 = 0.f, s3 = 0.f;
    for (int k = lane; k < HID; k += 32) {
        const float xv = x[k];
        s0 = fmaf(xv, Wg1[k * NH + warp],     s0);
        s1 = fmaf(xv, Wg1[k * NH + warp + 8], s1);
        s2 = fmaf(xv, Wg2[k * NH + warp],     s2);
        s3 = fmaf(xv, Wg2[k * NH + warp + 8], s3);
    }
#pragma unroll
    for (int off = 16; off; off >>= 1) {
        s0 += __shfl_down_sync(0xffffffffu, s0, off);
        s1 += __shfl_down_sync(0xffffffffu, s1, off);
        s2 += __shfl_down_sync(0xffffffffu, s2, off);
        s3 += __shfl_down_sync(0xffffffffu, s3, off);
    }
    if (lane == 0) {
        G1[t * NH + warp]     = 1.f / (1.f + expf(-(s0 + bg1[warp])));
        G1[t * NH + warp + 8] = 1.f / (1.f + expf(-(s1 + bg1[warp + 8])));
        G2[t * NH + warp]     = 1.f / (1.f + expf(-(s2 + bg2[warp])));
        G2[t * NH + warp + 8] = 1.f / (1.f + expf(-(s3 + bg2[warp + 8])));
    }
}

// ---------------- fused flash attention + g2 + LN + g1 ---------------------
// BM=BN=64, 256 threads arranged 16x16. Thread (ty,tx):
//   scores:  rows 4ty..4ty+3  x  cols {tx+16c, c=0..3}
//   output:  rows 4ty..4ty+3  x  cols 8tx..8tx+7
// V tile is prefetched global->registers during softmax, then stored to smem
// after the barrier: the V global-load latency hides behind exp/shuffle work.
#define ATT_SMEM_FLOATS (64 * 128 + 64 * 132 + 64 * 68 + 64)
#define ATT_SMEM_BYTES  (ATT_SMEM_FLOATS * 4)

__global__ __launch_bounds__(256, 1)
void attn_kernel(const float* __restrict__ Q,   // [T, 2048]
                 const float* __restrict__ Km,  // [T, 512]
                 const float* __restrict__ Vm,  // [T, 512]
                 const float* __restrict__ G1,  // [T, 16]
                 const float* __restrict__ G2,  // [T, 16]
                 const float* __restrict__ gamma,
                 const float* __restrict__ beta,
                 float* __restrict__ O)         // [T, 2048]
{
    extern __shared__ float sm[];
    float* Qs  = sm;                       // 64 x 128
    float* KVs = Qs + 64 * 128;            // 64 x 132 (padded): K then V
    float* Ps  = KVs + 64 * 132;           // 64 x 68  (padded)
    float* sg2 = Ps + 64 * 68;             // 64

    const int qtile = blockIdx.x;
    const int h     = blockIdx.y;
    const int b     = blockIdx.z;
    const int hk    = h >> 2;
    const int q0    = qtile * 64;
    const int tbase = b * S_LEN;
    const int tid   = threadIdx.x;
    const int ty    = tid >> 4;
    const int tx    = tid & 15;

    // load Q tile
    for (int i = tid; i < 64 * 32; i += 256) {
        const int r = i >> 5, c4 = (i & 31) << 2;
        *(float4*)&Qs[r * 128 + c4] =
            *(const float4*)&Q[(size_t)(tbase + q0 + r) * QDIM + h * HD + c4];
    }

    float m_i[4], l_i[4], acc[4][8];
#pragma unroll
    for (int i = 0; i < 4; i++) {
        m_i[i] = -1e30f;
        l_i[i] = 0.f;
#pragma unroll
        for (int j = 0; j < 8; j++) acc[i][j] = 0.f;
    }

    const float scale = 0.08838834764831845f;   // 1/sqrt(128)
    const int jend = q0 + 64;

    for (int j0 = 0; j0 < jend; j0 += 64) {
        __syncthreads();   // prior V reads done / Q tile loaded
        // load K tile (+ g2 for keys)
        for (int i = tid; i < 64 * 32; i += 256) {
            const int r = i >> 5, c4 = (i & 31) << 2;
            *(float4*)&KVs[r * 132 + c4] =
                *(const float4*)&Km[(size_t)(tbase + j0 + r) * KVDIM + hk * HD + c4];
        }
        if (tid < 64) sg2[tid] = G2[(size_t)(tbase + j0 + tid) * NH + h];
        __syncthreads();

        // scores
        float s[4][4];
#pragma unroll
        for (int i = 0; i < 4; i++)
#pragma unroll
            for (int c = 0; c < 4; c++) s[i][c] = 0.f;

        for (int d = 0; d < 128; d += 4) {
            float4 qv[4], kv[4];
#pragma unroll
            for (int i = 0; i < 4; i++) qv[i] = *(float4*)&Qs[(4 * ty + i) * 128 + d];
#pragma unroll
            for (int c = 0; c < 4; c++) kv[c] = *(float4*)&KVs[(tx + 16 * c) * 132 + d];
#pragma unroll
            for (int i = 0; i < 4; i++)
#pragma unroll
                for (int c = 0; c < 4; c++) {
                    s[i][c] = fmaf(qv[i].x, kv[c].x, s[i][c]);
                    s[i][c] = fmaf(qv[i].y, kv[c].y, s[i][c]);
                    s[i][c] = fmaf(qv[i].z, kv[c].z, s[i][c]);
                    s[i][c] = fmaf(qv[i].w, kv[c].w, s[i][c]);
                }
        }

        // prefetch V tile into registers NOW — latency hides behind softmax
        float4 vreg[8];
#pragma unroll
        for (int t8 = 0; t8 < 8; t8++) {
            const int i = tid + t8 * 256;
            const int r = i >> 5, c4 = (i & 31) << 2;
            vreg[t8] = *(const float4*)&Vm[(size_t)(tbase + j0 + r) * KVDIM + hk * HD + c4];
        }

        const bool diag = (j0 == q0);
#pragma unroll
        for (int i = 0; i < 4; i++)
#pragma unroll
            for (int c = 0; c < 4; c++) {
                s[i][c] *= scale;
                if (diag && (tx + 16 * c > 4 * ty + i)) s[i][c] = -1e30f;
            }

        // online softmax update
        float m_new[4], alpha[4];
#pragma unroll
        for (int i = 0; i < 4; i++) {
            float rm = fmaxf(fmaxf(s[i][0], s[i][1]), fmaxf(s[i][2], s[i][3]));
#pragma unroll
            for (int off = 8; off; off >>= 1)
                rm = fmaxf(rm, __shfl_xor_sync(0xffffffffu, rm, off, 16));
            m_new[i] = fmaxf(m_i[i], rm);
            alpha[i] = expf(m_i[i] - m_new[i]);
            float lsum = 0.f;
#pragma unroll
            for (int c = 0; c < 4; c++) {
                s[i][c] = expf(s[i][c] - m_new[i]);
                lsum += s[i][c];
            }
#pragma unroll
            for (int off = 8; off; off >>= 1)
                lsum += __shfl_xor_sync(0xffffffffu, lsum, off, 16);
            m_i[i] = m_new[i];
            l_i[i] = l_i[i] * alpha[i] + lsum;
#pragma unroll
            for (int j = 0; j < 8; j++) acc[i][j] *= alpha[i];
        }

        // write P (with value gate g2 folded in, AFTER the softmax row-sum)
#pragma unroll
        for (int i = 0; i < 4; i++)
#pragma unroll
            for (int c = 0; c < 4; c++)
                Ps[(4 * ty + i) * 68 + tx + 16 * c] = s[i][c] * sg2[tx + 16 * c];
        __syncthreads();   // P written, K reads finished

        // V registers -> smem (overwrites K tile; data already on-chip)
#pragma unroll
        for (int t8 = 0; t8 < 8; t8++) {
            const int i = tid + t8 * 256;
            const int r = i >> 5, c4 = (i & 31) << 2;
            *(float4*)&KVs[r * 132 + c4] = vreg[t8];
        }
        __syncthreads();

        // acc += P @ V
        for (int c = 0; c < 64; c++) {
            float pv[4];
#pragma unroll
            for (int i = 0; i < 4; i++) pv[i] = Ps[(4 * ty + i) * 68 + c];
            const float4 v0 = *(float4*)&KVs[c * 132 + 8 * tx];
            const float4 v1 = *(float4*)&KVs[c * 132 + 8 * tx + 4];
#pragma unroll
            for (int i = 0; i < 4; i++) {
                acc[i][0] = fmaf(pv[i], v0.x, acc[i][0]);
                acc[i][1] = fmaf(pv[i], v0.y, acc[i][1]);
                acc[i][2] = fmaf(pv[i], v0.z, acc[i][2]);
                acc[i][3] = fmaf(pv[i], v0.w, acc[i][3]);
                acc[i][4] = fmaf(pv[i], v1.x, acc[i][4]);
                acc[i][5] = fmaf(pv[i], v1.y, acc[i][5]);
                acc[i][6] = fmaf(pv[i], v1.z, acc[i][6]);
                acc[i][7] = fmaf(pv[i], v1.w, acc[i][7]);
            }
        }
    }

    // epilogue: normalize by l, per-head LayerNorm over 128 dims, *g1, store
#pragma unroll
    for (int i = 0; i < 4; i++) {
        const float inv_l = 1.f / l_i[i];
        float x[8];
        float lsum = 0.f;
#pragma unroll
        for (int j = 0; j < 8; j++) {
            x[j] = acc[i][j] * inv_l;
            lsum += x[j];
        }
#pragma unroll
        for (int off = 8; off; off >>= 1)
            lsum += __shfl_xor_sync(0xffffffffu, lsum, off, 16);
        const float mu = lsum * (1.f / 128.f);
        float vsum = 0.f;
#pragma unroll
        for (int j = 0; j < 8; j++) {
            const float dfc = x[j] - mu;
            vsum += dfc * dfc;
        }
#pragma unroll
        for (int off = 8; off; off >>= 1)
            vsum += __shfl_xor_sync(0xffffffffu, vsum, off, 16);
        const float rstd = rsqrtf(vsum * (1.f / 128.f) + 1e-5f);

        const int qi = q0 + 4 * ty + i;
        const float g1v = G1[(size_t)(tbase + qi) * NH + h];
        float y[8];
#pragma unroll
        for (int j = 0; j < 8; j++) {
            const int col = 8 * tx + j;
            y[j] = ((x[j] - mu) * rstd * gamma[col] + beta[col]) * g1v;
        }
        float4* op = (float4*)&O[(size_t)(tbase + qi) * QDIM + h * HD + 8 * tx];
        op[0] = make_float4(y[0], y[1], y[2], y[3]);
        op[1] = make_float4(y[4], y[5], y[6], y[7]);
    }
}

// ---------------- launch ---------------------------------------------------
extern "C" void kernel_launch(void* const* d_in, const int* in_sizes, int n_in,
                              void* d_out, int out_size) {
    const float* X     = (const float*)d_in[0];
    const int*   pos   = (const int*)d_in[1];
    const float* Wq    = (const float*)d_in[2];
    const float* Wk    = (const float*)d_in[3];
    const float* Wv    = (const float*)d_in[4];
    const float* Wo    = (const float*)d_in[5];
    const float* Wg1   = (const float*)d_in[6];
    const float* bg1   = (const float*)d_in[7];
    const float* Wg2   = (const float*)d_in[8];
    const float* bg2   = (const float*)d_in[9];
    const float* gamma = (const float*)d_in[10];
    const float* beta  = (const float*)d_in[11];
    float* out = (float*)d_out;

    void *pQ, *pK, *pV, *pG1, *pG2, *pO;
    cudaGetSymbolAddress(&pQ,  g_Q);
    cudaGetSymbolAddress(&pK,  g_K);
    cudaGetSymbolAddress(&pV,  g_V);
    cudaGetSymbolAddress(&pG1, g_G1);
    cudaGetSymbolAddress(&pG2, g_G2);
    cudaGetSymbolAddress(&pO,  g_O);
    float* Qp  = (float*)pQ;
    float* Kp  = (float*)pK;
    float* Vp  = (float*)pV;
    float* G1p = (float*)pG1;
    float* G2p = (float*)pG2;
    float* Op  = (float*)pO;

    // fused QKV projection (24 col-tiles x 32 row-tiles)
    sgemm_qkv<<<dim3(24, TOK / 128), 256>>>(X, Wq, Wk, Wv, Qp, Kp, Vp);
    // gates
    gates_kernel<<<TOK, 256>>>(X, Wg1, bg1, Wg2, bg2, G1p, G2p);
    // RoPE (in place)
    rope_kernel<<<4096, 256>>>(Qp, pos, NH);
    rope_kernel<<<1024, 256>>>(Kp, pos, NKV);
    // fused attention + g2 + LN + g1
    cudaFuncSetAttribute(attn_kernel, cudaFuncAttributeMaxDynamicSharedMemorySize,
                         ATT_SMEM_BYTES);
    attn_kernel<<<dim3(S_LEN / 64, NH, BATCH), 256, ATT_SMEM_BYTES>>>(
        Qp, Kp, Vp, G1p, G2p, gamma, beta, Op);
    // output projection
    sgemm128<<<dim3(HID / 128, TOK / 128), 256>>>(Op, Wo, out, TOK, HID, HID);
}

// round 8
// speedup vs baseline: 2.3065x; 2.3065x over previous
#include <cuda_runtime.h>
#include <cuda_fp16.h>
#include <math.h>
#include <cstdint>

#define S_LEN 2048
#define BATCH 2
#define TOK   (BATCH * S_LEN)   // 4096
#define HID   2048
#define NH    16
#define NKV   4
#define HD    128
#define QDIM  (NH * HD)         // 2048
#define KVDIM (NKV * HD)        // 512
#define NQKV  (QDIM + 2 * KVDIM) // 3072

// ---------------- scratch (static device arrays; no allocs) ----------------
__device__ float g_Q[TOK * QDIM];
__device__ float g_K[TOK * KVDIM];
__device__ float g_V[TOK * KVDIM];
__device__ float g_G1[TOK * NH];
__device__ float g_G2[TOK * NH];
__device__ float g_O[TOK * QDIM];
__device__ float g_RT[S_LEN * 128];          // cos[64] | sin[64] per position
__device__ __half g_Xh[TOK * HID];
__device__ __half g_Xl[TOK * HID];
__device__ __half g_Oh[TOK * QDIM];
__device__ __half g_Ol[TOK * QDIM];
__device__ __half g_WqkvTh[NQKV * HID];      // [n][k] transposed
__device__ __half g_WqkvTl[NQKV * HID];
__device__ __half g_WoTh[HID * QDIM];        // [n=2048][k=2048]
__device__ __half g_WoTl[HID * QDIM];

// ---------------- PTX helpers (baseline ISA only: sm_80-era) ---------------
__device__ __forceinline__ uint32_t smem_u32(const void* p) {
    uint32_t a;
    asm("{ .reg .u64 t; cvta.to.shared.u64 t, %1; cvt.u32.u64 %0, t; }"
        : "=r"(a) : "l"(p));
    return a;
}
__device__ __forceinline__ void cp16(uint32_t s, const void* g) {
    asm volatile("cp.async.cg.shared.global [%0], [%1], 16;" :: "r"(s), "l"(g));
}
#define CP_COMMIT() asm volatile("cp.async.commit_group;" ::: "memory")
#define CP_WAIT1()  asm volatile("cp.async.wait_group 1;" ::: "memory")
#define CP_WAIT0()  asm volatile("cp.async.wait_group 0;" ::: "memory")

__device__ __forceinline__ void ldsm4(uint32_t* r, uint32_t a) {
    asm volatile("ldmatrix.sync.aligned.m8n8.x4.shared.b16 {%0,%1,%2,%3}, [%4];"
                 : "=r"(r[0]), "=r"(r[1]), "=r"(r[2]), "=r"(r[3]) : "r"(a));
}
__device__ __forceinline__ void mma16816(float* d, const uint32_t* a, const uint32_t* b) {
    asm volatile("mma.sync.aligned.m16n8k16.row.col.f32.f16.f16.f32 "
                 "{%0,%1,%2,%3}, {%4,%5,%6,%7}, {%8,%9}, {%0,%1,%2,%3};"
                 : "+f"(d[0]), "+f"(d[1]), "+f"(d[2]), "+f"(d[3])
                 : "r"(a[0]), "r"(a[1]), "r"(a[2]), "r"(a[3]), "r"(b[0]), "r"(b[1]));
}

// ---------------- split: fp32 -> (fp16 hi, fp16 lo) ------------------------
__global__ void split_kernel(const float4* __restrict__ in,
                             uint2* __restrict__ hi, uint2* __restrict__ lo, int n4) {
    for (int i = blockIdx.x * blockDim.x + threadIdx.x; i < n4;
         i += gridDim.x * blockDim.x) {
        const float4 v = in[i];
        const __half h0 = __float2half_rn(v.x);
        const __half h1 = __float2half_rn(v.y);
        const __half h2 = __float2half_rn(v.z);
        const __half h3 = __float2half_rn(v.w);
        const __half l0 = __float2half_rn(v.x - __half2float(h0));
        const __half l1 = __float2half_rn(v.y - __half2float(h1));
        const __half l2 = __float2half_rn(v.z - __half2float(h2));
        const __half l3 = __float2half_rn(v.w - __half2float(h3));
        uint2 hw, lw;
        hw.x = (uint32_t)__half_as_ushort(h0) | ((uint32_t)__half_as_ushort(h1) << 16);
        hw.y = (uint32_t)__half_as_ushort(h2) | ((uint32_t)__half_as_ushort(h3) << 16);
        lw.x = (uint32_t)__half_as_ushort(l0) | ((uint32_t)__half_as_ushort(l1) << 16);
        lw.y = (uint32_t)__half_as_ushort(l2) | ((uint32_t)__half_as_ushort(l3) << 16);
        hi[i] = hw;
        lo[i] = lw;
    }
}

// ---------------- weight transpose + split: W[K,N] -> WT[N,K] hi/lo --------
__global__ void wqkv_tsplit(const float* __restrict__ Wq, const float* __restrict__ Wk,
                            const float* __restrict__ Wv,
                            __half* __restrict__ WTh, __half* __restrict__ WTl) {
    __shared__ float t[32][33];
    const int k0 = blockIdx.x * 32;
    const int n0 = blockIdx.y * 32;
    const float* src; int srcN, ncol;
    if (n0 < QDIM)              { src = Wq; srcN = QDIM;  ncol = n0; }
    else if (n0 < QDIM + KVDIM) { src = Wk; srcN = KVDIM; ncol = n0 - QDIM; }
    else                        { src = Wv; srcN = KVDIM; ncol = n0 - QDIM - KVDIM; }
    const int tx = threadIdx.x, ty = threadIdx.y;  // 32 x 8
#pragma unroll
    for (int j = 0; j < 32; j += 8)
        t[ty + j][tx] = src[(size_t)(k0 + ty + j) * srcN + ncol + tx];
    __syncthreads();
#pragma unroll
    for (int j = 0; j < 32; j += 8) {
        const float v = t[tx][ty + j];
        const __half h = __float2half_rn(v);
        const __half l = __float2half_rn(v - __half2float(h));
        const size_t o = (size_t)(n0 + ty + j) * HID + k0 + tx;
        WTh[o] = h;
        WTl[o] = l;
    }
}

__global__ void wo_tsplit(const float* __restrict__ Wo,
                          __half* __restrict__ WTh, __half* __restrict__ WTl) {
    __shared__ float t[32][33];
    const int k0 = blockIdx.x * 32;
    const int n0 = blockIdx.y * 32;
    const int tx = threadIdx.x, ty = threadIdx.y;
#pragma unroll
    for (int j = 0; j < 32; j += 8)
        t[ty + j][tx] = Wo[(size_t)(k0 + ty + j) * HID + n0 + tx];
    __syncthreads();
#pragma unroll
    for (int j = 0; j < 32; j += 8) {
        const float v = t[tx][ty + j];
        const __half h = __float2half_rn(v);
        const __half l = __float2half_rn(v - __half2float(h));
        const size_t o = (size_t)(n0 + ty + j) * QDIM + k0 + tx;
        WTh[o] = h;
        WTl[o] = l;
    }
}

// ---------------- HMMA split-fp16 GEMM: 128x128 tile, K chunks of 32 -------
// A: [M][K] fp16 hi/lo (K-major);  B: [N][K] fp16 hi/lo (K-major, pre-transposed)
// C(fp32) = Ah*Bh + Ah*Bl + Al*Bh   (fp32 accumulate in registers)
// smem: 2 stages x 4 tiles x [128 rows x 40 halves(80B)] = 81920 bytes.
#define TILE_B   10240               // one 128x40-half tile
#define GSTAGE_B (4 * TILE_B)        // 40960
#define GEMM_SMEM (2 * GSTAGE_B)     // 81920

__device__ __forceinline__ void gemm_hmma_tile(
    const __half* __restrict__ Ah, const __half* __restrict__ Al,
    const __half* __restrict__ Bh, const __half* __restrict__ Bl,
    float* __restrict__ C, int ldc, int K, int brow, int bn, int bcolC)
{
    extern __shared__ char smem[];
    const uint32_t sb = smem_u32(smem);

    const int tid  = threadIdx.x;
    const int wid  = tid >> 5;
    const int lane = tid & 31;
    const int wm = (wid & 3) * 32;    // warp row offset in tile
    const int wn = (wid >> 2) * 64;   // warp col offset in tile

    float acc[2][8][4];
#pragma unroll
    for (int mt = 0; mt < 2; mt++)
#pragma unroll
        for (int nt = 0; nt < 8; nt++)
#pragma unroll
            for (int q = 0; q < 4; q++) acc[mt][nt][q] = 0.f;

    const size_t rowB = (size_t)K * 2;  // bytes per source row
    const char* gAh = (const char*)(Ah + (size_t)brow * K);
    const char* gAl = (const char*)(Al + (size_t)brow * K);
    const char* gBh = (const char*)(Bh + (size_t)bn * K);
    const char* gBl = (const char*)(Bl + (size_t)bn * K);

    const int r  = tid >> 1;          // 0..127
    const int j0 = (tid & 1) * 2;     // 16B chunk pair
    const uint32_t sdst = (uint32_t)(r * 80);
    const size_t gsrc_row = (size_t)r * rowB;

    auto load_stage = [&](int st, int c) {
        const size_t kb = (size_t)c * 64;   // 32 halves
        const uint32_t s0 = sb + st * GSTAGE_B + sdst;
#pragma unroll
        for (int jj = 0; jj < 2; jj++) {
            const int j = j0 + jj;
            const uint32_t so = s0 + j * 16;
            const size_t go = gsrc_row + kb + j * 16;
            cp16(so,              gAh + go);
            cp16(so + TILE_B,     gAl + go);
            cp16(so + 2 * TILE_B, gBh + go);
            cp16(so + 3 * TILE_B, gBl + go);
        }
        CP_COMMIT();
    };

    const int nchunk = K / 32;
    load_stage(0, 0);
    for (int c = 0; c < nchunk; c++) {
        if (c + 1 < nchunk) { load_stage((c + 1) & 1, c + 1); CP_WAIT1(); }
        else                { CP_WAIT0(); }
        __syncthreads();

        const uint32_t st_base = sb + (c & 1) * GSTAGE_B;
        const uint32_t lrow = (uint32_t)((lane & 15) * 80 + ((lane >> 4) * 16));
#pragma unroll
        for (int kk = 0; kk < 2; kk++) {
            const uint32_t kb = kk * 32;   // byte offset of k16 step
            uint32_t ah[2][4], al[2][4], bh[8][2], bl[8][2];
#pragma unroll
            for (int mt = 0; mt < 2; mt++) {
                const uint32_t ra = st_base + (wm + 16 * mt) * 80 + lrow + kb;
                ldsm4(ah[mt], ra);
                ldsm4(al[mt], ra + TILE_B);
            }
#pragma unroll
            for (int nt2 = 0; nt2 < 4; nt2++) {
                const uint32_t rb = st_base + 2 * TILE_B + (wn + 16 * nt2) * 80 + lrow + kb;
                uint32_t t[4];
                ldsm4(t, rb);
                bh[2 * nt2][0] = t[0]; bh[2 * nt2 + 1][0] = t[1];
                bh[2 * nt2][1] = t[2]; bh[2 * nt2 + 1][1] = t[3];
                ldsm4(t, rb + TILE_B);
                bl[2 * nt2][0] = t[0]; bl[2 * nt2 + 1][0] = t[1];
                bl[2 * nt2][1] = t[2]; bl[2 * nt2 + 1][1] = t[3];
            }
#pragma unroll
            for (int mt = 0; mt < 2; mt++)
#pragma unroll
                for (int nt = 0; nt < 8; nt++) {
                    mma16816(acc[mt][nt], ah[mt], bh[nt]);
                    mma16816(acc[mt][nt], ah[mt], bl[nt]);
                    mma16816(acc[mt][nt], al[mt], bh[nt]);
                }
        }
        __syncthreads();
    }

    // epilogue: d0,d1 -> (row, col..col+1), d2,d3 -> (row+8, ..)
#pragma unroll
    for (int mt = 0; mt < 2; mt++) {
        const int r0 = brow + wm + 16 * mt + (lane >> 2);
#pragma unroll
        for (int nt = 0; nt < 8; nt++) {
            const int cc = bcolC + wn + 8 * nt + 2 * (lane & 3);
            float2* p0 = (float2*)(C + (size_t)r0 * ldc + cc);
            *p0 = make_float2(acc[mt][nt][0], acc[mt][nt][1]);
            float2* p1 = (float2*)(C + (size_t)(r0 + 8) * ldc + cc);
            *p1 = make_float2(acc[mt][nt][2], acc[mt][nt][3]);
        }
    }
}

__global__ __launch_bounds__(256)
void gemm_qkv_tc(const __half* Ah, const __half* Al,
                 const __half* Bh, const __half* Bl,
                 float* Q, float* Kd, float* Vd) {
    const int ct = blockIdx.x;      // 0..23
    float* C; int ldc, bcolC;
    if (ct < 16)      { C = Q;  ldc = QDIM;  bcolC = ct * 128; }
    else if (ct < 20) { C = Kd; ldc = KVDIM; bcolC = (ct - 16) * 128; }
    else              { C = Vd; ldc = KVDIM; bcolC = (ct - 20) * 128; }
    gemm_hmma_tile(Ah, Al, Bh, Bl, C, ldc, HID, blockIdx.y * 128, ct * 128, bcolC);
}

__global__ __launch_bounds__(256)
void gemm_o_tc(const __half* Ah, const __half* Al,
               const __half* Bh, const __half* Bl, float* C) {
    gemm_hmma_tile(Ah, Al, Bh, Bl, C, HID, QDIM,
                   blockIdx.y * 128, blockIdx.x * 128, blockIdx.x * 128);
}

// ---------------- RoPE: fp64 table once, then bandwidth-bound apply --------
__global__ void rope_table(const int* __restrict__ pos_ids, float* __restrict__ tab) {
    const int i = blockIdx.x * blockDim.x + threadIdx.x;
    if (i >= S_LEN * 64) return;
    const int s = i >> 6, d = i & 63;
    const int pos = pos_ids[s];
    const double invf = exp(-(double)d * (9.210340371976184 / 64.0));
    const double ang  = fmod((double)pos * invf, 6.283185307179586);
    float sn, cs;
    sincosf((float)ang, &sn, &cs);
    tab[s * 128 + d]      = cs;
    tab[s * 128 + 64 + d] = sn;
}

__global__ void rope_apply(float* __restrict__ X, const float* __restrict__ tab,
                           int nheads) {
    const int total = TOK * nheads * 64;
    for (int idx = blockIdx.x * blockDim.x + threadIdx.x; idx < total;
         idx += gridDim.x * blockDim.x) {
        const int d    = idx & 63;
        const int rest = idx >> 6;
        const int h    = rest % nheads;
        const int t    = rest / nheads;
        const int s    = t & (S_LEN - 1);
        const float cs = tab[s * 128 + d];
        const float sn = tab[s * 128 + 64 + d];
        float* base = X + (size_t)t * (nheads * HD) + h * HD;
        const float x0 = base[d];
        const float x1 = base[d + 64];
        base[d]      = x0 * cs - x1 * sn;
        base[d + 64] = x1 * cs + x0 * sn;
    }
}

// ---------------- gates: sigmoid(X @ Wg + bg), [T,16] each -----------------
__global__ void gates_kernel(const float* __restrict__ X,
                             const float* __restrict__ Wg1, const float* __restrict__ bg1,
                             const float* __restrict__ Wg2, const float* __restrict__ bg2,
                             float* __restrict__ G1, float* __restrict__ G2) {
    const int t    = blockIdx.x;
    const int warp = threadIdx.x >> 5;
    const int lane = threadIdx.x & 31;
    const float* x = X + (size_t)t * HID;
    float s0 = 0.f, s1 = 0.f, s2 = 0.f, s3 = 0.f;
    for (int k = lane; k < HID; k += 32) {
        const float xv = x[k];
        s0 = fmaf(xv, Wg1[k * NH + warp],     s0);
        s1 = fmaf(xv, Wg1[k * NH + warp + 8], s1);
        s2 = fmaf(xv, Wg2[k * NH + warp],     s2);
        s3 = fmaf(xv, Wg2[k * NH + warp + 8], s3);
    }
#pragma unroll
    for (int off = 16; off; off >>= 1) {
        s0 += __shfl_down_sync(0xffffffffu, s0, off);
        s1 += __shfl_down_sync(0xffffffffu, s1, off);
        s2 += __shfl_down_sync(0xffffffffu, s2, off);
        s3 += __shfl_down_sync(0xffffffffu, s3, off);
    }
    if (lane == 0) {
        G1[t * NH + warp]     = 1.f / (1.f + expf(-(s0 + bg1[warp])));
        G1[t * NH + warp + 8] = 1.f / (1.f + expf(-(s1 + bg1[warp + 8])));
        G2[t * NH + warp]     = 1.f / (1.f + expf(-(s2 + bg2[warp])));
        G2[t * NH + warp + 8] = 1.f / (1.f + expf(-(s3 + bg2[warp + 8])));
    }
}

// ---------------- fused flash attention + g2 + LN + g1 ---------------------
#define ATT_SMEM_FLOATS (64 * 128 + 64 * 132 + 64 * 68 + 64)
#define ATT_SMEM_BYTES  (ATT_SMEM_FLOATS * 4)

__global__ __launch_bounds__(256, 1)
void attn_kernel(const float* __restrict__ Q,
                 const float* __restrict__ Km,
                 const float* __restrict__ Vm,
                 const float* __restrict__ G1,
                 const float* __restrict__ G2,
                 const float* __restrict__ gamma,
                 const float* __restrict__ beta,
                 float* __restrict__ O)
{
    extern __shared__ float sm[];
    float* Qs  = sm;
    float* KVs = Qs + 64 * 128;
    float* Ps  = KVs + 64 * 132;
    float* sg2 = Ps + 64 * 68;

    const int qtile = blockIdx.x;
    const int h     = blockIdx.y;
    const int b     = blockIdx.z;
    const int hk    = h >> 2;
    const int q0    = qtile * 64;
    const int tbase = b * S_LEN;
    const int tid   = threadIdx.x;
    const int ty    = tid >> 4;
    const int tx    = tid & 15;

    for (int i = tid; i < 64 * 32; i += 256) {
        const int r = i >> 5, c4 = (i & 31) << 2;
        *(float4*)&Qs[r * 128 + c4] =
            *(const float4*)&Q[(size_t)(tbase + q0 + r) * QDIM + h * HD + c4];
    }

    float m_i[4], l_i[4], acc[4][8];
#pragma unroll
    for (int i = 0; i < 4; i++) {
        m_i[i] = -1e30f;
        l_i[i] = 0.f;
#pragma unroll
        for (int j = 0; j < 8; j++) acc[i][j] = 0.f;
    }

    const float scale = 0.08838834764831845f;
    const int jend = q0 + 64;

    for (int j0 = 0; j0 < jend; j0 += 64) {
        __syncthreads();
        for (int i = tid; i < 64 * 32; i += 256) {
            const int r = i >> 5, c4 = (i & 31) << 2;
            *(float4*)&KVs[r * 132 + c4] =
                *(const float4*)&Km[(size_t)(tbase + j0 + r) * KVDIM + hk * HD + c4];
        }
        if (tid < 64) sg2[tid] = G2[(size_t)(tbase + j0 + tid) * NH + h];
        __syncthreads();

        float s[4][4];
#pragma unroll
        for (int i = 0; i < 4; i++)
#pragma unroll
            for (int c = 0; c < 4; c++) s[i][c] = 0.f;

        for (int d = 0; d < 128; d += 4) {
            float4 qv[4], kv[4];
#pragma unroll
            for (int i = 0; i < 4; i++) qv[i] = *(float4*)&Qs[(4 * ty + i) * 128 + d];
#pragma unroll
            for (int c = 0; c < 4; c++) kv[c] = *(float4*)&KVs[(tx + 16 * c) * 132 + d];
#pragma unroll
            for (int i = 0; i < 4; i++)
#pragma unroll
                for (int c = 0; c < 4; c++) {
                    s[i][c] = fmaf(qv[i].x, kv[c].x, s[i][c]);
                    s[i][c] = fmaf(qv[i].y, kv[c].y, s[i][c]);
                    s[i][c] = fmaf(qv[i].z, kv[c].z, s[i][c]);
                    s[i][c] = fmaf(qv[i].w, kv[c].w, s[i][c]);
                }
        }

        float4 vreg[8];
#pragma unroll
        for (int t8 = 0; t8 < 8; t8++) {
            const int i = tid + t8 * 256;
            const int r = i >> 5, c4 = (i & 31) << 2;
            vreg[t8] = *(const float4*)&Vm[(size_t)(tbase + j0 + r) * KVDIM + hk * HD + c4];
        }

        const bool diag = (j0 == q0);
#pragma unroll
        for (int i = 0; i < 4; i++)
#pragma unroll
            for (int c = 0; c < 4; c++) {
                s[i][c] *= scale;
                if (diag && (tx + 16 * c > 4 * ty + i)) s[i][c] = -1e30f;
            }

        float m_new[4], alpha[4];
#pragma unroll
        for (int i = 0; i < 4; i++) {
            float rm = fmaxf(fmaxf(s[i][0], s[i][1]), fmaxf(s[i][2], s[i][3]));
#pragma unroll
            for (int off = 8; off; off >>= 1)
                rm = fmaxf(rm, __shfl_xor_sync(0xffffffffu, rm, off, 16));
            m_new[i] = fmaxf(m_i[i], rm);
            alpha[i] = __expf(m_i[i] - m_new[i]);
            float lsum = 0.f;
#pragma unroll
            for (int c = 0; c < 4; c++) {
                s[i][c] = __expf(s[i][c] - m_new[i]);
                lsum += s[i][c];
            }
#pragma unroll
            for (int off = 8; off; off >>= 1)
                lsum += __shfl_xor_sync(0xffffffffu, lsum, off, 16);
            m_i[i] = m_new[i];
            l_i[i] = l_i[i] * alpha[i] + lsum;
#pragma unroll
            for (int j = 0; j < 8; j++) acc[i][j] *= alpha[i];
        }

#pragma unroll
        for (int i = 0; i < 4; i++)
#pragma unroll
            for (int c = 0; c < 4; c++)
                Ps[(4 * ty + i) * 68 + tx + 16 * c] = s[i][c] * sg2[tx + 16 * c];
        __syncthreads();

#pragma unroll
        for (int t8 = 0; t8 < 8; t8++) {
            const int i = tid + t8 * 256;
            const int r = i >> 5, c4 = (i & 31) << 2;
            *(float4*)&KVs[r * 132 + c4] = vreg[t8];
        }
        __syncthreads();

        for (int c = 0; c < 64; c++) {
            float pv[4];
#pragma unroll
            for (int i = 0; i < 4; i++) pv[i] = Ps[(4 * ty + i) * 68 + c];
            const float4 v0 = *(float4*)&KVs[c * 132 + 8 * tx];
            const float4 v1 = *(float4*)&KVs[c * 132 + 8 * tx + 4];
#pragma unroll
            for (int i = 0; i < 4; i++) {
                acc[i][0] = fmaf(pv[i], v0.x, acc[i][0]);
                acc[i][1] = fmaf(pv[i], v0.y, acc[i][1]);
                acc[i][2] = fmaf(pv[i], v0.z, acc[i][2]);
                acc[i][3] = fmaf(pv[i], v0.w, acc[i][3]);
                acc[i][4] = fmaf(pv[i], v1.x, acc[i][4]);
                acc[i][5] = fmaf(pv[i], v1.y, acc[i][5]);
                acc[i][6] = fmaf(pv[i], v1.z, acc[i][6]);
                acc[i][7] = fmaf(pv[i], v1.w, acc[i][7]);
            }
        }
    }

#pragma unroll
    for (int i = 0; i < 4; i++) {
        const float inv_l = 1.f / l_i[i];
        float x[8];
        float lsum = 0.f;
#pragma unroll
        for (int j = 0; j < 8; j++) {
            x[j] = acc[i][j] * inv_l;
            lsum += x[j];
        }
#pragma unroll
        for (int off = 8; off; off >>= 1)
            lsum += __shfl_xor_sync(0xffffffffu, lsum, off, 16);
        const float mu = lsum * (1.f / 128.f);
        float vsum = 0.f;
#pragma unroll
        for (int j = 0; j < 8; j++) {
            const float dfc = x[j] - mu;
            vsum += dfc * dfc;
        }
#pragma unroll
        for (int off = 8; off; off >>= 1)
            vsum += __shfl_xor_sync(0xffffffffu, vsum, off, 16);
        const float rstd = rsqrtf(vsum * (1.f / 128.f) + 1e-5f);

        const int qi = q0 + 4 * ty + i;
        const float g1v = G1[(size_t)(tbase + qi) * NH + h];
        float y[8];
#pragma unroll
        for (int j = 0; j < 8; j++) {
            const int col = 8 * tx + j;
            y[j] = ((x[j] - mu) * rstd * gamma[col] + beta[col]) * g1v;
        }
        float4* op = (float4*)&O[(size_t)(tbase + qi) * QDIM + h * HD + 8 * tx];
        op[0] = make_float4(y[0], y[1], y[2], y[3]);
        op[1] = make_float4(y[4], y[5], y[6], y[7]);
    }
}

// ---------------- launch ---------------------------------------------------
extern "C" void kernel_launch(void* const* d_in, const int* in_sizes, int n_in,
                              void* d_out, int out_size) {
    const float* X     = (const float*)d_in[0];
    const int*   pos   = (const int*)d_in[1];
    const float* Wq    = (const float*)d_in[2];
    const float* Wk    = (const float*)d_in[3];
    const float* Wv    = (const float*)d_in[4];
    const float* Wo    = (const float*)d_in[5];
    const float* Wg1   = (const float*)d_in[6];
    const float* bg1   = (const float*)d_in[7];
    const float* Wg2   = (const float*)d_in[8];
    const float* bg2   = (const float*)d_in[9];
    const float* gamma = (const float*)d_in[10];
    const float* beta  = (const float*)d_in[11];
    float* out = (float*)d_out;

    void *pQ, *pK, *pV, *pG1, *pG2, *pO, *pRT;
    void *pXh, *pXl, *pOh, *pOl, *pWh, *pWl, *pWoh, *pWol;
    cudaGetSymbolAddress(&pQ,  g_Q);
    cudaGetSymbolAddress(&pK,  g_K);
    cudaGetSymbolAddress(&pV,  g_V);
    cudaGetSymbolAddress(&pG1, g_G1);
    cudaGetSymbolAddress(&pG2, g_G2);
    cudaGetSymbolAddress(&pO,  g_O);
    cudaGetSymbolAddress(&pRT, g_RT);
    cudaGetSymbolAddress(&pXh, g_Xh);
    cudaGetSymbolAddress(&pXl, g_Xl);
    cudaGetSymbolAddress(&pOh, g_Oh);
    cudaGetSymbolAddress(&pOl, g_Ol);
    cudaGetSymbolAddress(&pWh, g_WqkvTh);
    cudaGetSymbolAddress(&pWl, g_WqkvTl);
    cudaGetSymbolAddress(&pWoh, g_WoTh);
    cudaGetSymbolAddress(&pWol, g_WoTl);

    float* Qp  = (float*)pQ;
    float* Kp  = (float*)pK;
    float* Vp  = (float*)pV;
    float* G1p = (float*)pG1;
    float* G2p = (float*)pG2;
    float* Op  = (float*)pO;
    float* RTp = (float*)pRT;

    // 1. split activations X -> fp16 hi/lo; rope table; weight transposes
    split_kernel<<<512, 256>>>((const float4*)X, (uint2*)pXh, (uint2*)pXl,
                               TOK * HID / 4);
    rope_table<<<(S_LEN * 64 + 255) / 256, 256>>>(pos, RTp);
    wqkv_tsplit<<<dim3(HID / 32, NQKV / 32), dim3(32, 8)>>>(
        Wq, Wk, Wv, (__half*)pWh, (__half*)pWl);
    wo_tsplit<<<dim3(QDIM / 32, HID / 32), dim3(32, 8)>>>(
        Wo, (__half*)pWoh, (__half*)pWol);
    // 2. gates (reads fp32 X)
    gates_kernel<<<TOK, 256>>>(X, Wg1, bg1, Wg2, bg2, G1p, G2p);
    // 3. QKV projection on tensor cores (HMMA split-fp16)
    cudaFuncSetAttribute(gemm_qkv_tc, cudaFuncAttributeMaxDynamicSharedMemorySize,
                         GEMM_SMEM);
    gemm_qkv_tc<<<dim3(NQKV / 128, TOK / 128), 256, GEMM_SMEM>>>(
        (const __half*)pXh, (const __half*)pXl,
        (const __half*)pWh, (const __half*)pWl, Qp, Kp, Vp);
    // 4. RoPE
    rope_apply<<<2048, 256>>>(Qp, RTp, NH);
    rope_apply<<<512, 256>>>(Kp, RTp, NKV);
    // 5. fused attention + g2 + LN + g1
    cudaFuncSetAttribute(attn_kernel, cudaFuncAttributeMaxDynamicSharedMemorySize,
                         ATT_SMEM_BYTES);
    attn_kernel<<<dim3(S_LEN / 64, NH, BATCH), 256, ATT_SMEM_BYTES>>>(
        Qp, Kp, Vp, G1p, G2p, gamma, beta, Op);
    // 6. split attention output, 7. output projection on tensor cores
    split_kernel<<<512, 256>>>((const float4*)Op, (uint2*)pOh, (uint2*)pOl,
                               TOK * QDIM / 4);
    cudaFuncSetAttribute(gemm_o_tc, cudaFuncAttributeMaxDynamicSharedMemorySize,
                         GEMM_SMEM);
    gemm_o_tc<<<dim3(HID / 128, TOK / 128), 256, GEMM_SMEM>>>(
        (const __half*)pOh, (const __half*)pOl,
        (const __half*)pWoh, (const __half*)pWol, out);
}

// round 9
// speedup vs baseline: 3.3461x; 1.4508x over previous
#include <cuda_runtime.h>
#include <cuda_fp16.h>
#include <math.h>
#include <cstdint>

#define S_LEN 2048
#define BATCH 2
#define TOK   (BATCH * S_LEN)   // 4096
#define HID   2048
#define NH    16
#define NKV   4
#define HD    128
#define QDIM  (NH * HD)         // 2048
#define KVDIM (NKV * HD)        // 512
#define NQKV  (QDIM + 2 * KVDIM) // 3072

// ---------------- scratch (static device arrays; no allocs) ----------------
__device__ float g_Q[TOK * QDIM];
__device__ float g_K[TOK * KVDIM];
__device__ float g_V[TOK * KVDIM];
__device__ float g_G1[TOK * NH];
__device__ float g_G2[TOK * NH];
__device__ float g_RT[S_LEN * 128];
__device__ __half g_Xh[TOK * HID];
__device__ __half g_Xl[TOK * HID];
__device__ __half g_Oh[TOK * QDIM];
__device__ __half g_Ol[TOK * QDIM];
__device__ __half g_Qh[TOK * QDIM];
__device__ __half g_Ql[TOK * QDIM];
__device__ __half g_Kh[TOK * KVDIM];
__device__ __half g_Kl[TOK * KVDIM];
__device__ __half g_VTh[BATCH * KVDIM * S_LEN];  // [b*512 + c][s]
__device__ __half g_VTl[BATCH * KVDIM * S_LEN];
__device__ __half g_WqkvTh[NQKV * HID];
__device__ __half g_WqkvTl[NQKV * HID];
__device__ __half g_WoTh[HID * QDIM];
__device__ __half g_WoTl[HID * QDIM];

// ---------------- PTX helpers (baseline ISA only) ---------------------------
__device__ __forceinline__ uint32_t smem_u32(const void* p) {
    uint32_t a;
    asm("{ .reg .u64 t; cvta.to.shared.u64 t, %1; cvt.u32.u64 %0, t; }"
        : "=r"(a) : "l"(p));
    return a;
}
__device__ __forceinline__ void cp16(uint32_t s, const void* g) {
    asm volatile("cp.async.cg.shared.global [%0], [%1], 16;" :: "r"(s), "l"(g));
}
#define CP_COMMIT() asm volatile("cp.async.commit_group;" ::: "memory")
#define CP_WAIT1()  asm volatile("cp.async.wait_group 1;" ::: "memory")
#define CP_WAIT0()  asm volatile("cp.async.wait_group 0;" ::: "memory")

__device__ __forceinline__ void ldsm4(uint32_t* r, uint32_t a) {
    asm volatile("ldmatrix.sync.aligned.m8n8.x4.shared.b16 {%0,%1,%2,%3}, [%4];"
                 : "=r"(r[0]), "=r"(r[1]), "=r"(r[2]), "=r"(r[3]) : "r"(a));
}
__device__ __forceinline__ void mma16816(float* d, const uint32_t* a, const uint32_t* b) {
    asm volatile("mma.sync.aligned.m16n8k16.row.col.f32.f16.f16.f32 "
                 "{%0,%1,%2,%3}, {%4,%5,%6,%7}, {%8,%9}, {%0,%1,%2,%3};"
                 : "+f"(d[0]), "+f"(d[1]), "+f"(d[2]), "+f"(d[3])
                 : "r"(a[0]), "r"(a[1]), "r"(a[2]), "r"(a[3]), "r"(b[0]), "r"(b[1]));
}
__device__ __forceinline__ uint32_t packh2(__half a, __half b) {
    __half2 h = __halves2half2(a, b);
    return *(uint32_t*)&h;
}

// ---------------- split: fp32 -> (fp16 hi, fp16 lo) ------------------------
__global__ void split_kernel(const float4* __restrict__ in,
                             uint2* __restrict__ hi, uint2* __restrict__ lo, int n4) {
    for (int i = blockIdx.x * blockDim.x + threadIdx.x; i < n4;
         i += gridDim.x * blockDim.x) {
        const float4 v = in[i];
        const __half h0 = __float2half_rn(v.x);
        const __half h1 = __float2half_rn(v.y);
        const __half h2 = __float2half_rn(v.z);
        const __half h3 = __float2half_rn(v.w);
        const __half l0 = __float2half_rn(v.x - __half2float(h0));
        const __half l1 = __float2half_rn(v.y - __half2float(h1));
        const __half l2 = __float2half_rn(v.z - __half2float(h2));
        const __half l3 = __float2half_rn(v.w - __half2float(h3));
        uint2 hw, lw;
        hw.x = packh2(h0, h1); hw.y = packh2(h2, h3);
        lw.x = packh2(l0, l1); lw.y = packh2(l2, l3);
        hi[i] = hw;
        lo[i] = lw;
    }
}

// ---------------- weight transpose + split ---------------------------------
__global__ void wqkv_tsplit(const float* __restrict__ Wq, const float* __restrict__ Wk,
                            const float* __restrict__ Wv,
                            __half* __restrict__ WTh, __half* __restrict__ WTl) {
    __shared__ float t[32][33];
    const int k0 = blockIdx.x * 32;
    const int n0 = blockIdx.y * 32;
    const float* src; int srcN, ncol;
    if (n0 < QDIM)              { src = Wq; srcN = QDIM;  ncol = n0; }
    else if (n0 < QDIM + KVDIM) { src = Wk; srcN = KVDIM; ncol = n0 - QDIM; }
    else                        { src = Wv; srcN = KVDIM; ncol = n0 - QDIM - KVDIM; }
    const int tx = threadIdx.x, ty = threadIdx.y;
#pragma unroll
    for (int j = 0; j < 32; j += 8)
        t[ty + j][tx] = src[(size_t)(k0 + ty + j) * srcN + ncol + tx];
    __syncthreads();
#pragma unroll
    for (int j = 0; j < 32; j += 8) {
        const float v = t[tx][ty + j];
        const __half h = __float2half_rn(v);
        const __half l = __float2half_rn(v - __half2float(h));
        const size_t o = (size_t)(n0 + ty + j) * HID + k0 + tx;
        WTh[o] = h;
        WTl[o] = l;
    }
}

__global__ void wo_tsplit(const float* __restrict__ Wo,
                          __half* __restrict__ WTh, __half* __restrict__ WTl) {
    __shared__ float t[32][33];
    const int k0 = blockIdx.x * 32;
    const int n0 = blockIdx.y * 32;
    const int tx = threadIdx.x, ty = threadIdx.y;
#pragma unroll
    for (int j = 0; j < 32; j += 8)
        t[ty + j][tx] = Wo[(size_t)(k0 + ty + j) * HID + n0 + tx];
    __syncthreads();
#pragma unroll
    for (int j = 0; j < 32; j += 8) {
        const float v = t[tx][ty + j];
        const __half h = __float2half_rn(v);
        const __half l = __float2half_rn(v - __half2float(h));
        const size_t o = (size_t)(n0 + ty + j) * QDIM + k0 + tx;
        WTh[o] = h;
        WTl[o] = l;
    }
}

// ---------------- V transpose + split: V[T,512] -> VT[b*512+c][s] hi/lo ----
__global__ void vt_tsplit(const float* __restrict__ V,
                          __half* __restrict__ VTh, __half* __restrict__ VTl) {
    __shared__ float t[32][33];
    const int c0 = blockIdx.x * 32;
    const int s0 = blockIdx.y * 32;
    const int b  = blockIdx.z;
    const int tx = threadIdx.x, ty = threadIdx.y;
#pragma unroll
    for (int j = 0; j < 32; j += 8)
        t[ty + j][tx] = V[(size_t)(b * S_LEN + s0 + ty + j) * KVDIM + c0 + tx];
    __syncthreads();
#pragma unroll
    for (int j = 0; j < 32; j += 8) {
        const float v = t[tx][ty + j];
        const __half h = __float2half_rn(v);
        const __half l = __float2half_rn(v - __half2float(h));
        const size_t o = (size_t)(b * KVDIM + c0 + ty + j) * S_LEN + s0 + tx;
        VTh[o] = h;
        VTl[o] = l;
    }
}

// ---------------- HMMA split-fp16 GEMM (validated R8) ----------------------
#define TILE_B   10240
#define GSTAGE_B (4 * TILE_B)
#define GEMM_SMEM (2 * GSTAGE_B)

__device__ __forceinline__ void gemm_hmma_tile(
    const __half* __restrict__ Ah, const __half* __restrict__ Al,
    const __half* __restrict__ Bh, const __half* __restrict__ Bl,
    float* __restrict__ C, int ldc, int K, int brow, int bn, int bcolC)
{
    extern __shared__ char smem[];
    const uint32_t sb = smem_u32(smem);

    const int tid  = threadIdx.x;
    const int wid  = tid >> 5;
    const int lane = tid & 31;
    const int wm = (wid & 3) * 32;
    const int wn = (wid >> 2) * 64;

    float acc[2][8][4];
#pragma unroll
    for (int mt = 0; mt < 2; mt++)
#pragma unroll
        for (int nt = 0; nt < 8; nt++)
#pragma unroll
            for (int q = 0; q < 4; q++) acc[mt][nt][q] = 0.f;

    const size_t rowB = (size_t)K * 2;
    const char* gAh = (const char*)(Ah + (size_t)brow * K);
    const char* gAl = (const char*)(Al + (size_t)brow * K);
    const char* gBh = (const char*)(Bh + (size_t)bn * K);
    const char* gBl = (const char*)(Bl + (size_t)bn * K);

    const int r  = tid >> 1;
    const int j0 = (tid & 1) * 2;
    const uint32_t sdst = (uint32_t)(r * 80);
    const size_t gsrc_row = (size_t)r * rowB;

    auto load_stage = [&](int st, int c) {
        const size_t kb = (size_t)c * 64;
        const uint32_t s0 = sb + st * GSTAGE_B + sdst;
#pragma unroll
        for (int jj = 0; jj < 2; jj++) {
            const int j = j0 + jj;
            const uint32_t so = s0 + j * 16;
            const size_t go = gsrc_row + kb + j * 16;
            cp16(so,              gAh + go);
            cp16(so + TILE_B,     gAl + go);
            cp16(so + 2 * TILE_B, gBh + go);
            cp16(so + 3 * TILE_B, gBl + go);
        }
        CP_COMMIT();
    };

    const int nchunk = K / 32;
    load_stage(0, 0);
    for (int c = 0; c < nchunk; c++) {
        if (c + 1 < nchunk) { load_stage((c + 1) & 1, c + 1); CP_WAIT1(); }
        else                { CP_WAIT0(); }
        __syncthreads();

        const uint32_t st_base = sb + (c & 1) * GSTAGE_B;
        const uint32_t lrow = (uint32_t)((lane & 15) * 80 + ((lane >> 4) * 16));
#pragma unroll
        for (int kk = 0; kk < 2; kk++) {
            const uint32_t kb = kk * 32;
            uint32_t ah[2][4], al[2][4], bh[8][2], bl[8][2];
#pragma unroll
            for (int mt = 0; mt < 2; mt++) {
                const uint32_t ra = st_base + (wm + 16 * mt) * 80 + lrow + kb;
                ldsm4(ah[mt], ra);
                ldsm4(al[mt], ra + TILE_B);
            }
#pragma unroll
            for (int nt2 = 0; nt2 < 4; nt2++) {
                const uint32_t rb = st_base + 2 * TILE_B + (wn + 16 * nt2) * 80 + lrow + kb;
                uint32_t t[4];
                ldsm4(t, rb);
                bh[2 * nt2][0] = t[0]; bh[2 * nt2 + 1][0] = t[1];
                bh[2 * nt2][1] = t[2]; bh[2 * nt2 + 1][1] = t[3];
                ldsm4(t, rb + TILE_B);
                bl[2 * nt2][0] = t[0]; bl[2 * nt2 + 1][0] = t[1];
                bl[2 * nt2][1] = t[2]; bl[2 * nt2 + 1][1] = t[3];
            }
#pragma unroll
            for (int mt = 0; mt < 2; mt++)
#pragma unroll
                for (int nt = 0; nt < 8; nt++) {
                    mma16816(acc[mt][nt], ah[mt], bh[nt]);
                    mma16816(acc[mt][nt], ah[mt], bl[nt]);
                    mma16816(acc[mt][nt], al[mt], bh[nt]);
                }
        }
        __syncthreads();
    }

#pragma unroll
    for (int mt = 0; mt < 2; mt++) {
        const int r0 = brow + wm + 16 * mt + (lane >> 2);
#pragma unroll
        for (int nt = 0; nt < 8; nt++) {
            const int cc = bcolC + wn + 8 * nt + 2 * (lane & 3);
            float2* p0 = (float2*)(C + (size_t)r0 * ldc + cc);
            *p0 = make_float2(acc[mt][nt][0], acc[mt][nt][1]);
            float2* p1 = (float2*)(C + (size_t)(r0 + 8) * ldc + cc);
            *p1 = make_float2(acc[mt][nt][2], acc[mt][nt][3]);
        }
    }
}

__global__ __launch_bounds__(256)
void gemm_qkv_tc(const __half* Ah, const __half* Al,
                 const __half* Bh, const __half* Bl,
                 float* Q, float* Kd, float* Vd) {
    const int ct = blockIdx.x;
    float* C; int ldc, bcolC;
    if (ct < 16)      { C = Q;  ldc = QDIM;  bcolC = ct * 128; }
    else if (ct < 20) { C = Kd; ldc = KVDIM; bcolC = (ct - 16) * 128; }
    else              { C = Vd; ldc = KVDIM; bcolC = (ct - 20) * 128; }
    gemm_hmma_tile(Ah, Al, Bh, Bl, C, ldc, HID, blockIdx.y * 128, ct * 128, bcolC);
}

__global__ __launch_bounds__(256)
void gemm_o_tc(const __half* Ah, const __half* Al,
               const __half* Bh, const __half* Bl, float* C) {
    gemm_hmma_tile(Ah, Al, Bh, Bl, C, HID, QDIM,
                   blockIdx.y * 128, blockIdx.x * 128, blockIdx.x * 128);
}

// ---------------- RoPE --------------------------------------------------
__global__ void rope_table(const int* __restrict__ pos_ids, float* __restrict__ tab) {
    const int i = blockIdx.x * blockDim.x + threadIdx.x;
    if (i >= S_LEN * 64) return;
    const int s = i >> 6, d = i & 63;
    const int pos = pos_ids[s];
    const double invf = exp(-(double)d * (9.210340371976184 / 64.0));
    const double ang  = fmod((double)pos * invf, 6.283185307179586);
    float sn, cs;
    sincosf((float)ang, &sn, &cs);
    tab[s * 128 + d]      = cs;
    tab[s * 128 + 64 + d] = sn;
}

__global__ void rope_apply(float* __restrict__ X, const float* __restrict__ tab,
                           int nheads) {
    const int total = TOK * nheads * 64;
    for (int idx = blockIdx.x * blockDim.x + threadIdx.x; idx < total;
         idx += gridDim.x * blockDim.x) {
        const int d    = idx & 63;
        const int rest = idx >> 6;
        const int h    = rest % nheads;
        const int t    = rest / nheads;
        const int s    = t & (S_LEN - 1);
        const float cs = tab[s * 128 + d];
        const float sn = tab[s * 128 + 64 + d];
        float* base = X + (size_t)t * (nheads * HD) + h * HD;
        const float x0 = base[d];
        const float x1 = base[d + 64];
        base[d]      = x0 * cs - x1 * sn;
        base[d + 64] = x1 * cs + x0 * sn;
    }
}

// ---------------- gates ------------------------------------------------
__global__ void gates_kernel(const float* __restrict__ X,
                             const float* __restrict__ Wg1, const float* __restrict__ bg1,
                             const float* __restrict__ Wg2, const float* __restrict__ bg2,
                             float* __restrict__ G1, float* __restrict__ G2) {
    const int t    = blockIdx.x;
    const int warp = threadIdx.x >> 5;
    const int lane = threadIdx.x & 31;
    const float* x = X + (size_t)t * HID;
    float s0 = 0.f, s1 = 0.f, s2 = 0.f, s3 = 0.f;
    for (int k = lane; k < HID; k += 32) {
        const float xv = x[k];
        s0 = fmaf(xv, Wg1[k * NH + warp],     s0);
        s1 = fmaf(xv, Wg1[k * NH + warp + 8], s1);
        s2 = fmaf(xv, Wg2[k * NH + warp],     s2);
        s3 = fmaf(xv, Wg2[k * NH + warp + 8], s3);
    }
#pragma unroll
    for (int off = 16; off; off >>= 1) {
        s0 += __shfl_down_sync(0xffffffffu, s0, off);
        s1 += __shfl_down_sync(0xffffffffu, s1, off);
        s2 += __shfl_down_sync(0xffffffffu, s2, off);
        s3 += __shfl_down_sync(0xffffffffu, s3, off);
    }
    if (lane == 0) {
        G1[t * NH + warp]     = 1.f / (1.f + expf(-(s0 + bg1[warp])));
        G1[t * NH + warp + 8] = 1.f / (1.f + expf(-(s1 + bg1[warp + 8])));
        G2[t * NH + warp]     = 1.f / (1.f + expf(-(s2 + bg2[warp])));
        G2[t * NH + warp + 8] = 1.f / (1.f + expf(-(s3 + bg2[warp + 8])));
    }
}

// ---------------- HMMA flash attention + g2 + LN + g1 ----------------------
// BM=128 q rows, BN=64 keys, 8 warps x 16 rows. 3-pass split-fp16 for both
// QK^T and PV. P converts D-frag -> A-frag in registers. Emits Oh/Ol fp16.
#define BM 128
#define BN 64
#define QSTR 272   // 136 halves per row (128 data + 8 pad)
#define VSTR 144   // 72 halves per row (64 data + 8 pad)
#define SQH_OFF 0
#define SQL_OFF 34816
#define SKH_OFF 69632
#define SKL_OFF 87040
#define SVH_OFF 104448
#define SVL_OFF 122880
#define SG2_OFF 141312
#define SGAM_OFF 141568
#define SBET_OFF 142080
#define ATTN_SMEM 142592

__global__ __launch_bounds__(256, 1)
void attn_hmma(const __half* __restrict__ Qh, const __half* __restrict__ Ql,
               const __half* __restrict__ Kh, const __half* __restrict__ Kl,
               const __half* __restrict__ VTh, const __half* __restrict__ VTl,
               const float* __restrict__ G1, const float* __restrict__ G2,
               const float* __restrict__ gamma, const float* __restrict__ beta,
               __half* __restrict__ Oh, __half* __restrict__ Ol)
{
    extern __shared__ char smem[];
    const uint32_t sb = smem_u32(smem);
    float* sG2  = (float*)(smem + SG2_OFF);
    float* sGam = (float*)(smem + SGAM_OFF);
    float* sBet = (float*)(smem + SBET_OFF);

    const int tid = threadIdx.x, wid = tid >> 5, lane = tid & 31;
    const int qt = blockIdx.x, h = blockIdx.y, b = blockIdx.z;
    const int hk = h >> 2;
    const int q0 = qt * BM;
    const int tbase = b * S_LEN;
    const int wrow = wid * 16;
    const int c2 = 2 * (lane & 3);

    if (tid < 128) { sGam[tid] = gamma[tid]; sBet[tid] = beta[tid]; }

    // Q tile (once)
    {
        const __half* gqh = Qh + (size_t)(tbase + q0) * QDIM + h * HD;
        const __half* gql = Ql + (size_t)(tbase + q0) * QDIM + h * HD;
#pragma unroll
        for (int t = 0; t < 8; t++) {
            const int idx = tid + t * 256;
            const int row = idx >> 4, cj = idx & 15;
            const uint32_t so = row * QSTR + cj * 16;
            cp16(sb + SQH_OFF + so, gqh + (size_t)row * QDIM + cj * 8);
            cp16(sb + SQL_OFF + so, gql + (size_t)row * QDIM + cj * 8);
        }
        CP_COMMIT();
    }

    float m_i[2] = {-1e30f, -1e30f};
    float l_i[2] = {0.f, 0.f};
    float oacc[16][4];
#pragma unroll
    for (int nt = 0; nt < 16; nt++)
#pragma unroll
        for (int q = 0; q < 4; q++) oacc[nt][q] = 0.f;

    const float scale = 0.08838834764831845f;
    const uint32_t lrowQ = (lane & 15) * QSTR + (lane >> 4) * 16;
    const uint32_t lrowV = (lane & 15) * VSTR + (lane >> 4) * 16;
    const int ntiles = (q0 + BM) / BN;

    for (int jt = 0; jt < ntiles; jt++) {
        const int j0 = jt * BN;
        {
            const __half* gkh = Kh + (size_t)(tbase + j0) * KVDIM + hk * HD;
            const __half* gkl = Kl + (size_t)(tbase + j0) * KVDIM + hk * HD;
#pragma unroll
            for (int t = 0; t < 4; t++) {
                const int idx = tid + t * 256;
                const int row = idx >> 4, cj = idx & 15;
                const uint32_t so = row * QSTR + cj * 16;
                cp16(sb + SKH_OFF + so, gkh + (size_t)row * KVDIM + cj * 8);
                cp16(sb + SKL_OFF + so, gkl + (size_t)row * KVDIM + cj * 8);
            }
            const size_t vrow0 = (size_t)(b * KVDIM + hk * HD) * S_LEN;
#pragma unroll
            for (int t = 0; t < 4; t++) {
                const int idx = tid + t * 256;
                const int row = idx >> 3, cj = idx & 7;
                const uint32_t so = row * VSTR + cj * 16;
                cp16(sb + SVH_OFF + so, VTh + vrow0 + (size_t)row * S_LEN + j0 + cj * 8);
                cp16(sb + SVL_OFF + so, VTl + vrow0 + (size_t)row * S_LEN + j0 + cj * 8);
            }
            CP_COMMIT();
        }
        if (tid < 64) sG2[tid] = G2[(size_t)(tbase + j0 + tid) * NH + h];
        CP_WAIT0();
        __syncthreads();

        if (j0 <= q0 + wrow + 15) {
            // ---- scores: S = Q K^T (3-pass split) ----
            float sacc[8][4];
#pragma unroll
            for (int nt = 0; nt < 8; nt++)
#pragma unroll
                for (int q = 0; q < 4; q++) sacc[nt][q] = 0.f;

#pragma unroll
            for (int kk = 0; kk < 8; kk++) {
                uint32_t ah[4], al[4];
                const uint32_t ra = sb + SQH_OFF + wrow * QSTR + lrowQ + kk * 32;
                ldsm4(ah, ra);
                ldsm4(al, ra + (SQL_OFF - SQH_OFF));
                uint32_t bh[8][2], bl[8][2];
#pragma unroll
                for (int n2 = 0; n2 < 4; n2++) {
                    const uint32_t rb = sb + SKH_OFF + (16 * n2) * QSTR + lrowQ + kk * 32;
                    uint32_t t4[4];
                    ldsm4(t4, rb);
                    bh[2*n2][0] = t4[0]; bh[2*n2+1][0] = t4[1];
                    bh[2*n2][1] = t4[2]; bh[2*n2+1][1] = t4[3];
                    ldsm4(t4, rb + (SKL_OFF - SKH_OFF));
                    bl[2*n2][0] = t4[0]; bl[2*n2+1][0] = t4[1];
                    bl[2*n2][1] = t4[2]; bl[2*n2+1][1] = t4[3];
                }
#pragma unroll
                for (int nt = 0; nt < 8; nt++) {
                    mma16816(sacc[nt], ah, bh[nt]);
                    mma16816(sacc[nt], ah, bl[nt]);
                    mma16816(sacc[nt], al, bh[nt]);
                }
            }

#pragma unroll
            for (int nt = 0; nt < 8; nt++)
#pragma unroll
                for (int q = 0; q < 4; q++) sacc[nt][q] *= scale;

            if (j0 + BN - 1 > q0 + wrow) {   // diagonal tile: mask
                const int r0g = q0 + wrow + (lane >> 2);
#pragma unroll
                for (int nt = 0; nt < 8; nt++)
#pragma unroll
                    for (int q = 0; q < 4; q++) {
                        const int col = j0 + 8 * nt + c2 + (q & 1);
                        const int row = r0g + (q >> 1) * 8;
                        if (col > row) sacc[nt][q] = -1e30f;
                    }
            }

            // ---- online softmax (rows in-warp; quad shuffles) ----
#pragma unroll
            for (int i = 0; i < 2; i++) {
                float rm = -1e30f;
#pragma unroll
                for (int nt = 0; nt < 8; nt++)
                    rm = fmaxf(rm, fmaxf(sacc[nt][2*i], sacc[nt][2*i+1]));
                rm = fmaxf(rm, __shfl_xor_sync(0xffffffffu, rm, 1));
                rm = fmaxf(rm, __shfl_xor_sync(0xffffffffu, rm, 2));
                const float mnew = fmaxf(m_i[i], rm);
                const float alpha = __expf(m_i[i] - mnew);
                float ls = 0.f;
#pragma unroll
                for (int nt = 0; nt < 8; nt++) {
                    sacc[nt][2*i]   = __expf(sacc[nt][2*i]   - mnew);
                    sacc[nt][2*i+1] = __expf(sacc[nt][2*i+1] - mnew);
                    ls += sacc[nt][2*i] + sacc[nt][2*i+1];
                }
                ls += __shfl_xor_sync(0xffffffffu, ls, 1);
                ls += __shfl_xor_sync(0xffffffffu, ls, 2);
                m_i[i] = mnew;
                l_i[i] = l_i[i] * alpha + ls;
#pragma unroll
                for (int nt = 0; nt < 16; nt++) {
                    oacc[nt][2*i]   *= alpha;
                    oacc[nt][2*i+1] *= alpha;
                }
            }

            // ---- gate by g2, split P, pack D-frag -> A-frag ----
            uint32_t pah[4][4], pal[4][4];
#pragma unroll
            for (int nt = 0; nt < 8; nt++) {
                const float g20 = sG2[8 * nt + c2];
                const float g21 = sG2[8 * nt + c2 + 1];
                const float p0 = sacc[nt][0] * g20;
                const float p1 = sacc[nt][1] * g21;
                const float p2 = sacc[nt][2] * g20;
                const float p3 = sacc[nt][3] * g21;
                const __half h0 = __float2half_rn(p0), h1 = __float2half_rn(p1);
                const __half h2 = __float2half_rn(p2), h3 = __float2half_rn(p3);
                const __half e0 = __float2half_rn(p0 - __half2float(h0));
                const __half e1 = __float2half_rn(p1 - __half2float(h1));
                const __half e2 = __float2half_rn(p2 - __half2float(h2));
                const __half e3 = __float2half_rn(p3 - __half2float(h3));
                const int t = nt >> 1;
                const int s = (nt & 1) * 2;
                pah[t][s]     = packh2(h0, h1);
                pah[t][s + 1] = packh2(h2, h3);
                pal[t][s]     = packh2(e0, e1);
                pal[t][s + 1] = packh2(e2, e3);
            }

            // ---- O += P V  (3-pass split) ----
#pragma unroll
            for (int nv2 = 0; nv2 < 8; nv2++) {
#pragma unroll
                for (int t = 0; t < 4; t++) {
                    uint32_t bvh[4], bvl[4];
                    const uint32_t rb = sb + SVH_OFF + (16 * nv2) * VSTR + lrowV + t * 32;
                    ldsm4(bvh, rb);
                    ldsm4(bvl, rb + (SVL_OFF - SVH_OFF));
                    uint32_t be[2], bo[2], bel[2], bol[2];
                    be[0] = bvh[0]; be[1] = bvh[2]; bo[0] = bvh[1]; bo[1] = bvh[3];
                    bel[0] = bvl[0]; bel[1] = bvl[2]; bol[0] = bvl[1]; bol[1] = bvl[3];
                    mma16816(oacc[2*nv2],     pah[t], be);
                    mma16816(oacc[2*nv2],     pah[t], bel);
                    mma16816(oacc[2*nv2],     pal[t], be);
                    mma16816(oacc[2*nv2+1],   pah[t], bo);
                    mma16816(oacc[2*nv2+1],   pah[t], bol);
                    mma16816(oacc[2*nv2+1],   pal[t], bo);
                }
            }
        }
        __syncthreads();
    }

    // ---- epilogue: /l, LayerNorm, *g1, emit fp16 hi/lo ----
#pragma unroll
    for (int i = 0; i < 2; i++) {
        const int row = q0 + wrow + (lane >> 2) + 8 * i;
        const float inv_l = 1.f / l_i[i];
        float x[32];
        float sum = 0.f;
#pragma unroll
        for (int nt = 0; nt < 16; nt++) {
            x[2*nt]   = oacc[nt][2*i]   * inv_l;
            x[2*nt+1] = oacc[nt][2*i+1] * inv_l;
            sum += x[2*nt] + x[2*nt+1];
        }
        sum += __shfl_xor_sync(0xffffffffu, sum, 1);
        sum += __shfl_xor_sync(0xffffffffu, sum, 2);
        const float mu = sum * (1.f / 128.f);
        float vs = 0.f;
#pragma unroll
        for (int j = 0; j < 32; j++) { const float d = x[j] - mu; vs += d * d; }
        vs += __shfl_xor_sync(0xffffffffu, vs, 1);
        vs += __shfl_xor_sync(0xffffffffu, vs, 2);
        const float rstd = rsqrtf(vs * (1.f / 128.f) + 1e-5f);
        const float g1v = G1[(size_t)(tbase + row) * NH + h];
        __half* oph = Oh + (size_t)(tbase + row) * QDIM + h * HD;
        __half* opl = Ol + (size_t)(tbase + row) * QDIM + h * HD;
#pragma unroll
        for (int nt = 0; nt < 16; nt++) {
            const int col = 8 * nt + c2;
            const float y0 = ((x[2*nt]   - mu) * rstd * sGam[col]     + sBet[col])     * g1v;
            const float y1 = ((x[2*nt+1] - mu) * rstd * sGam[col + 1] + sBet[col + 1]) * g1v;
            const __half h0 = __float2half_rn(y0), h1 = __float2half_rn(y1);
            const __half e0 = __float2half_rn(y0 - __half2float(h0));
            const __half e1 = __float2half_rn(y1 - __half2float(h1));
            *(uint32_t*)(oph + col) = packh2(h0, h1);
            *(uint32_t*)(opl + col) = packh2(e0, e1);
        }
    }
}

// ---------------- launch ---------------------------------------------------
extern "C" void kernel_launch(void* const* d_in, const int* in_sizes, int n_in,
                              void* d_out, int out_size) {
    const float* X     = (const float*)d_in[0];
    const int*   pos   = (const int*)d_in[1];
    const float* Wq    = (const float*)d_in[2];
    const float* Wk    = (const float*)d_in[3];
    const float* Wv    = (const float*)d_in[4];
    const float* Wo    = (const float*)d_in[5];
    const float* Wg1   = (const float*)d_in[6];
    const float* bg1   = (const float*)d_in[7];
    const float* Wg2   = (const float*)d_in[8];
    const float* bg2   = (const float*)d_in[9];
    const float* gamma = (const float*)d_in[10];
    const float* beta  = (const float*)d_in[11];
    float* out = (float*)d_out;

    void *pQ, *pK, *pV, *pG1, *pG2, *pRT;
    void *pXh, *pXl, *pOh, *pOl, *pWh, *pWl, *pWoh, *pWol;
    void *pQh, *pQl, *pKh, *pKl, *pVTh, *pVTl;
    cudaGetSymbolAddress(&pQ,  g_Q);
    cudaGetSymbolAddress(&pK,  g_K);
    cudaGetSymbolAddress(&pV,  g_V);
    cudaGetSymbolAddress(&pG1, g_G1);
    cudaGetSymbolAddress(&pG2, g_G2);
    cudaGetSymbolAddress(&pRT, g_RT);
    cudaGetSymbolAddress(&pXh, g_Xh);
    cudaGetSymbolAddress(&pXl, g_Xl);
    cudaGetSymbolAddress(&pOh, g_Oh);
    cudaGetSymbolAddress(&pOl, g_Ol);
    cudaGetSymbolAddress(&pWh, g_WqkvTh);
    cudaGetSymbolAddress(&pWl, g_WqkvTl);
    cudaGetSymbolAddress(&pWoh, g_WoTh);
    cudaGetSymbolAddress(&pWol, g_WoTl);
    cudaGetSymbolAddress(&pQh, g_Qh);
    cudaGetSymbolAddress(&pQl, g_Ql);
    cudaGetSymbolAddress(&pKh, g_Kh);
    cudaGetSymbolAddress(&pKl, g_Kl);
    cudaGetSymbolAddress(&pVTh, g_VTh);
    cudaGetSymbolAddress(&pVTl, g_VTl);

    float* Qp  = (float*)pQ;
    float* Kp  = (float*)pK;
    float* Vp  = (float*)pV;
    float* G1p = (float*)pG1;
    float* G2p = (float*)pG2;
    float* RTp = (float*)pRT;

    // prep: split X, rope table, weight transposes, gates
    split_kernel<<<512, 256>>>((const float4*)X, (uint2*)pXh, (uint2*)pXl,
                               TOK * HID / 4);
    rope_table<<<(S_LEN * 64 + 255) / 256, 256>>>(pos, RTp);
    wqkv_tsplit<<<dim3(HID / 32, NQKV / 32), dim3(32, 8)>>>(
        Wq, Wk, Wv, (__half*)pWh, (__half*)pWl);
    wo_tsplit<<<dim3(QDIM / 32, HID / 32), dim3(32, 8)>>>(
        Wo, (__half*)pWoh, (__half*)pWol);
    gates_kernel<<<TOK, 256>>>(X, Wg1, bg1, Wg2, bg2, G1p, G2p);

    // QKV projection (HMMA)
    cudaFuncSetAttribute(gemm_qkv_tc, cudaFuncAttributeMaxDynamicSharedMemorySize,
                         GEMM_SMEM);
    gemm_qkv_tc<<<dim3(NQKV / 128, TOK / 128), 256, GEMM_SMEM>>>(
        (const __half*)pXh, (const __half*)pXl,
        (const __half*)pWh, (const __half*)pWl, Qp, Kp, Vp);

    // RoPE (fp32 in place), then split Q/K to fp16 hi/lo; transpose+split V
    rope_apply<<<2048, 256>>>(Qp, RTp, NH);
    rope_apply<<<512, 256>>>(Kp, RTp, NKV);
    split_kernel<<<512, 256>>>((const float4*)Qp, (uint2*)pQh, (uint2*)pQl,
                               TOK * QDIM / 4);
    split_kernel<<<256, 256>>>((const float4*)Kp, (uint2*)pKh, (uint2*)pKl,
                               TOK * KVDIM / 4);
    vt_tsplit<<<dim3(KVDIM / 32, S_LEN / 32, BATCH), dim3(32, 8)>>>(
        Vp, (__half*)pVTh, (__half*)pVTl);

    // HMMA flash attention (emits Oh/Ol fp16 directly)
    cudaFuncSetAttribute(attn_hmma, cudaFuncAttributeMaxDynamicSharedMemorySize,
                         ATTN_SMEM);
    attn_hmma<<<dim3(S_LEN / BM, NH, BATCH), 256, ATTN_SMEM>>>(
        (const __half*)pQh, (const __half*)pQl,
        (const __half*)pKh, (const __half*)pKl,
        (const __half*)pVTh, (const __half*)pVTl,
        G1p, G2p, gamma, beta, (__half*)pOh, (__half*)pOl);

    // output projection (HMMA)
    cudaFuncSetAttribute(gemm_o_tc, cudaFuncAttributeMaxDynamicSharedMemorySize,
                         GEMM_SMEM);
    gemm_o_tc<<<dim3(HID / 128, TOK / 128), 256, GEMM_SMEM>>>(
        (const __half*)pOh, (const __half*)pOl,
        (const __half*)pWoh, (const __half*)pWol, out);
}

// round 13
// speedup vs baseline: 3.3697x; 1.0070x over previous
#include <cuda_runtime.h>
#include <cuda_fp16.h>
#include <math.h>
#include <cstdint>

#define S_LEN 2048
#define BATCH 2
#define TOK   (BATCH * S_LEN)   // 4096
#define HID   2048
#define NH    16
#define NKV   4
#define HD    128
#define QDIM  (NH * HD)         // 2048
#define KVDIM (NKV * HD)        // 512
#define NQKV  (QDIM + 2 * KVDIM) // 3072

// ---------------- scratch (static device arrays; no allocs) ----------------
__device__ float g_Q[TOK * QDIM];
__device__ float g_K[TOK * KVDIM];
__device__ float g_V[TOK * KVDIM];
__device__ float g_G1[TOK * NH];
__device__ float g_G2[TOK * NH];
__device__ float g_RT[S_LEN * 128];
__device__ __half g_Xh[TOK * HID];
__device__ __half g_Xl[TOK * HID];
__device__ __half g_Oh[TOK * QDIM];
__device__ __half g_Ol[TOK * QDIM];
__device__ __half g_Qh[TOK * QDIM];
__device__ __half g_Ql[TOK * QDIM];
__device__ __half g_Kh[TOK * KVDIM];
__device__ __half g_Kl[TOK * KVDIM];
__device__ __half g_VTh[BATCH * KVDIM * S_LEN];  // [b*512 + c][s]
__device__ __half g_VTl[BATCH * KVDIM * S_LEN];
__device__ __half g_WqkvTh[NQKV * HID];
__device__ __half g_WqkvTl[NQKV * HID];
__device__ __half g_WoTh[HID * QDIM];
__device__ __half g_WoTl[HID * QDIM];

// ---------------- PTX helpers (baseline ISA only) ---------------------------
__device__ __forceinline__ uint32_t smem_u32(const void* p) {
    uint32_t a;
    asm("{ .reg .u64 t; cvta.to.shared.u64 t, %1; cvt.u32.u64 %0, t; }"
        : "=r"(a) : "l"(p));
    return a;
}
__device__ __forceinline__ void cp16(uint32_t s, const void* g) {
    asm volatile("cp.async.cg.shared.global [%0], [%1], 16;" :: "r"(s), "l"(g));
}
#define CP_COMMIT() asm volatile("cp.async.commit_group;" ::: "memory")
#define CP_WAIT1()  asm volatile("cp.async.wait_group 1;" ::: "memory")
#define CP_WAIT0()  asm volatile("cp.async.wait_group 0;" ::: "memory")

__device__ __forceinline__ void ldsm4(uint32_t* r, uint32_t a) {
    asm volatile("ldmatrix.sync.aligned.m8n8.x4.shared.b16 {%0,%1,%2,%3}, [%4];"
                 : "=r"(r[0]), "=r"(r[1]), "=r"(r[2]), "=r"(r[3]) : "r"(a));
}
__device__ __forceinline__ void mma16816(float* d, const uint32_t* a, const uint32_t* b) {
    asm volatile("mma.sync.aligned.m16n8k16.row.col.f32.f16.f16.f32 "
                 "{%0,%1,%2,%3}, {%4,%5,%6,%7}, {%8,%9}, {%0,%1,%2,%3};"
                 : "+f"(d[0]), "+f"(d[1]), "+f"(d[2]), "+f"(d[3])
                 : "r"(a[0]), "r"(a[1]), "r"(a[2]), "r"(a[3]), "r"(b[0]), "r"(b[1]));
}
__device__ __forceinline__ uint32_t packh2(__half a, __half b) {
    __half2 h = __halves2half2(a, b);
    return *(uint32_t*)&h;
}

// ---------------- split: fp32 -> (fp16 hi, fp16 lo) ------------------------
__global__ void split_kernel(const float4* __restrict__ in,
                             uint2* __restrict__ hi, uint2* __restrict__ lo, int n4) {
    for (int i = blockIdx.x * blockDim.x + threadIdx.x; i < n4;
         i += gridDim.x * blockDim.x) {
        const float4 v = in[i];
        const __half h0 = __float2half_rn(v.x);
        const __half h1 = __float2half_rn(v.y);
        const __half h2 = __float2half_rn(v.z);
        const __half h3 = __float2half_rn(v.w);
        const __half l0 = __float2half_rn(v.x - __half2float(h0));
        const __half l1 = __float2half_rn(v.y - __half2float(h1));
        const __half l2 = __float2half_rn(v.z - __half2float(h2));
        const __half l3 = __float2half_rn(v.w - __half2float(h3));
        uint2 hw, lw;
        hw.x = packh2(h0, h1); hw.y = packh2(h2, h3);
        lw.x = packh2(l0, l1); lw.y = packh2(l2, l3);
        hi[i] = hw;
        lo[i] = lw;
    }
}

// ---------------- weight transpose + split ---------------------------------
__global__ void wqkv_tsplit(const float* __restrict__ Wq, const float* __restrict__ Wk,
                            const float* __restrict__ Wv,
                            __half* __restrict__ WTh, __half* __restrict__ WTl) {
    __shared__ float t[32][33];
    const int k0 = blockIdx.x * 32;
    const int n0 = blockIdx.y * 32;
    const float* src; int srcN, ncol;
    if (n0 < QDIM)              { src = Wq; srcN = QDIM;  ncol = n0; }
    else if (n0 < QDIM + KVDIM) { src = Wk; srcN = KVDIM; ncol = n0 - QDIM; }
    else                        { src = Wv; srcN = KVDIM; ncol = n0 - QDIM - KVDIM; }
    const int tx = threadIdx.x, ty = threadIdx.y;
#pragma unroll
    for (int j = 0; j < 32; j += 8)
        t[ty + j][tx] = src[(size_t)(k0 + ty + j) * srcN + ncol + tx];
    __syncthreads();
#pragma unroll
    for (int j = 0; j < 32; j += 8) {
        const float v = t[tx][ty + j];
        const __half h = __float2half_rn(v);
        const __half l = __float2half_rn(v - __half2float(h));
        const size_t o = (size_t)(n0 + ty + j) * HID + k0 + tx;
        WTh[o] = h;
        WTl[o] = l;
    }
}

__global__ void wo_tsplit(const float* __restrict__ Wo,
                          __half* __restrict__ WTh, __half* __restrict__ WTl) {
    __shared__ float t[32][33];
    const int k0 = blockIdx.x * 32;
    const int n0 = blockIdx.y * 32;
    const int tx = threadIdx.x, ty = threadIdx.y;
#pragma unroll
    for (int j = 0; j < 32; j += 8)
        t[ty + j][tx] = Wo[(size_t)(k0 + ty + j) * HID + n0 + tx];
    __syncthreads();
#pragma unroll
    for (int j = 0; j < 32; j += 8) {
        const float v = t[tx][ty + j];
        const __half h = __float2half_rn(v);
        const __half l = __float2half_rn(v - __half2float(h));
        const size_t o = (size_t)(n0 + ty + j) * QDIM + k0 + tx;
        WTh[o] = h;
        WTl[o] = l;
    }
}

// ---------------- V transpose + split --------------------------------------
__global__ void vt_tsplit(const float* __restrict__ V,
                          __half* __restrict__ VTh, __half* __restrict__ VTl) {
    __shared__ float t[32][33];
    const int c0 = blockIdx.x * 32;
    const int s0 = blockIdx.y * 32;
    const int b  = blockIdx.z;
    const int tx = threadIdx.x, ty = threadIdx.y;
#pragma unroll
    for (int j = 0; j < 32; j += 8)
        t[ty + j][tx] = V[(size_t)(b * S_LEN + s0 + ty + j) * KVDIM + c0 + tx];
    __syncthreads();
#pragma unroll
    for (int j = 0; j < 32; j += 8) {
        const float v = t[tx][ty + j];
        const __half h = __float2half_rn(v);
        const __half l = __float2half_rn(v - __half2float(h));
        const size_t o = (size_t)(b * KVDIM + c0 + ty + j) * S_LEN + s0 + tx;
        VTh[o] = h;
        VTl[o] = l;
    }
}

// ---------------- HMMA split-fp16 GEMM (validated R8/R9) --------------------
#define TILE_B   10240
#define GSTAGE_B (4 * TILE_B)
#define GEMM_SMEM (2 * GSTAGE_B)

__device__ __forceinline__ void gemm_hmma_tile(
    const __half* __restrict__ Ah, const __half* __restrict__ Al,
    const __half* __restrict__ Bh, const __half* __restrict__ Bl,
    float* __restrict__ C, int ldc, int K, int brow, int bn, int bcolC)
{
    extern __shared__ char smem[];
    const uint32_t sb = smem_u32(smem);

    const int tid  = threadIdx.x;
    const int wid  = tid >> 5;
    const int lane = tid & 31;
    const int wm = (wid & 3) * 32;
    const int wn = (wid >> 2) * 64;

    float acc[2][8][4];
#pragma unroll
    for (int mt = 0; mt < 2; mt++)
#pragma unroll
        for (int nt = 0; nt < 8; nt++)
#pragma unroll
            for (int q = 0; q < 4; q++) acc[mt][nt][q] = 0.f;

    const size_t rowB = (size_t)K * 2;
    const char* gAh = (const char*)(Ah + (size_t)brow * K);
    const char* gAl = (const char*)(Al + (size_t)brow * K);
    const char* gBh = (const char*)(Bh + (size_t)bn * K);
    const char* gBl = (const char*)(Bl + (size_t)bn * K);

    const int r  = tid >> 1;
    const int j0 = (tid & 1) * 2;
    const uint32_t sdst = (uint32_t)(r * 80);
    const size_t gsrc_row = (size_t)r * rowB;

    auto load_stage = [&](int st, int c) {
        const size_t kb = (size_t)c * 64;
        const uint32_t s0 = sb + st * GSTAGE_B + sdst;
#pragma unroll
        for (int jj = 0; jj < 2; jj++) {
            const int j = j0 + jj;
            const uint32_t so = s0 + j * 16;
            const size_t go = gsrc_row + kb + j * 16;
            cp16(so,              gAh + go);
            cp16(so + TILE_B,     gAl + go);
            cp16(so + 2 * TILE_B, gBh + go);
            cp16(so + 3 * TILE_B, gBl + go);
        }
        CP_COMMIT();
    };

    const int nchunk = K / 32;
    load_stage(0, 0);
    for (int c = 0; c < nchunk; c++) {
        if (c + 1 < nchunk) { load_stage((c + 1) & 1, c + 1); CP_WAIT1(); }
        else                { CP_WAIT0(); }
        __syncthreads();

        const uint32_t st_base = sb + (c & 1) * GSTAGE_B;
        const uint32_t lrow = (uint32_t)((lane & 15) * 80 + ((lane >> 4) * 16));
#pragma unroll
        for (int kk = 0; kk < 2; kk++) {
            const uint32_t kb = kk * 32;
            uint32_t ah[2][4], al[2][4], bh[8][2], bl[8][2];
#pragma unroll
            for (int mt = 0; mt < 2; mt++) {
                const uint32_t ra = st_base + (wm + 16 * mt) * 80 + lrow + kb;
                ldsm4(ah[mt], ra);
                ldsm4(al[mt], ra + TILE_B);
            }
#pragma unroll
            for (int nt2 = 0; nt2 < 4; nt2++) {
                const uint32_t rb = st_base + 2 * TILE_B + (wn + 16 * nt2) * 80 + lrow + kb;
                uint32_t t[4];
                ldsm4(t, rb);
                bh[2 * nt2][0] = t[0]; bh[2 * nt2 + 1][0] = t[1];
                bh[2 * nt2][1] = t[2]; bh[2 * nt2 + 1][1] = t[3];
                ldsm4(t, rb + TILE_B);
                bl[2 * nt2][0] = t[0]; bl[2 * nt2 + 1][0] = t[1];
                bl[2 * nt2][1] = t[2]; bl[2 * nt2 + 1][1] = t[3];
            }
#pragma unroll
            for (int mt = 0; mt < 2; mt++)
#pragma unroll
                for (int nt = 0; nt < 8; nt++) {
                    mma16816(acc[mt][nt], ah[mt], bh[nt]);
                    mma16816(acc[mt][nt], ah[mt], bl[nt]);
                    mma16816(acc[mt][nt], al[mt], bh[nt]);
                }
        }
        __syncthreads();
    }

#pragma unroll
    for (int mt = 0; mt < 2; mt++) {
        const int r0 = brow + wm + 16 * mt + (lane >> 2);
#pragma unroll
        for (int nt = 0; nt < 8; nt++) {
            const int cc = bcolC + wn + 8 * nt + 2 * (lane & 3);
            float2* p0 = (float2*)(C + (size_t)r0 * ldc + cc);
            *p0 = make_float2(acc[mt][nt][0], acc[mt][nt][1]);
            float2* p1 = (float2*)(C + (size_t)(r0 + 8) * ldc + cc);
            *p1 = make_float2(acc[mt][nt][2], acc[mt][nt][3]);
        }
    }
}

__global__ __launch_bounds__(256)
void gemm_qkv_tc(const __half* Ah, const __half* Al,
                 const __half* Bh, const __half* Bl,
                 float* Q, float* Kd, float* Vd) {
    const int ct = blockIdx.x;
    float* C; int ldc, bcolC;
    if (ct < 16)      { C = Q;  ldc = QDIM;  bcolC = ct * 128; }
    else if (ct < 20) { C = Kd; ldc = KVDIM; bcolC = (ct - 16) * 128; }
    else              { C = Vd; ldc = KVDIM; bcolC = (ct - 20) * 128; }
    gemm_hmma_tile(Ah, Al, Bh, Bl, C, ldc, HID, blockIdx.y * 128, ct * 128, bcolC);
}

__global__ __launch_bounds__(256)
void gemm_o_tc(const __half* Ah, const __half* Al,
               const __half* Bh, const __half* Bl, float* C) {
    gemm_hmma_tile(Ah, Al, Bh, Bl, C, HID, QDIM,
                   blockIdx.y * 128, blockIdx.x * 128, blockIdx.x * 128);
}

// ---------------- RoPE table ------------------------------------------------
__global__ void rope_table(const int* __restrict__ pos_ids, float* __restrict__ tab) {
    const int i = blockIdx.x * blockDim.x + threadIdx.x;
    if (i >= S_LEN * 64) return;
    const int s = i >> 6, d = i & 63;
    const int pos = pos_ids[s];
    const double invf = exp(-(double)d * (9.210340371976184 / 64.0));
    const double ang  = fmod((double)pos * invf, 6.283185307179586);
    float sn, cs;
    sincosf((float)ang, &sn, &cs);
    tab[s * 128 + d]      = cs;
    tab[s * 128 + 64 + d] = sn;
}

// ---------------- fused rope + split: fp32 X -> fp16 hi/lo ------------------
__global__ void rope_split(const float* __restrict__ X, const float* __restrict__ tab,
                           __half* __restrict__ Xh, __half* __restrict__ Xl,
                           int nheads) {
    const int total = TOK * nheads * 16;   // 4 pairs per thread
    for (int idx = blockIdx.x * blockDim.x + threadIdx.x; idx < total;
         idx += gridDim.x * blockDim.x) {
        const int d4   = idx & 15;
        const int rest = idx >> 4;
        const int h    = rest % nheads;
        const int t    = rest / nheads;
        const int s    = t & (S_LEN - 1);
        const int d    = d4 * 4;
        const float4 c4 = *(const float4*)&tab[s * 128 + d];
        const float4 s4 = *(const float4*)&tab[s * 128 + 64 + d];
        const float* base = X + (size_t)t * (nheads * HD) + h * HD;
        const float4 x0 = *(const float4*)&base[d];
        const float4 x1 = *(const float4*)&base[d + 64];
        float y0[4], y1[4];
        y0[0] = x0.x * c4.x - x1.x * s4.x;  y1[0] = x1.x * c4.x + x0.x * s4.x;
        y0[1] = x0.y * c4.y - x1.y * s4.y;  y1[1] = x1.y * c4.y + x0.y * s4.y;
        y0[2] = x0.z * c4.z - x1.z * s4.z;  y1[2] = x1.z * c4.z + x0.z * s4.z;
        y0[3] = x0.w * c4.w - x1.w * s4.w;  y1[3] = x1.w * c4.w + x0.w * s4.w;
        const size_t ob = (size_t)t * (nheads * HD) + h * HD;
        uint2 hv, lv;
        __half hh[4], hl[4];
#pragma unroll
        for (int j = 0; j < 4; j++) {
            hh[j] = __float2half_rn(y0[j]);
            hl[j] = __float2half_rn(y0[j] - __half2float(hh[j]));
        }
        hv.x = packh2(hh[0], hh[1]); hv.y = packh2(hh[2], hh[3]);
        lv.x = packh2(hl[0], hl[1]); lv.y = packh2(hl[2], hl[3]);
        *(uint2*)(Xh + ob + d) = hv;
        *(uint2*)(Xl + ob + d) = lv;
#pragma unroll
        for (int j = 0; j < 4; j++) {
            hh[j] = __float2half_rn(y1[j]);
            hl[j] = __float2half_rn(y1[j] - __half2float(hh[j]));
        }
        hv.x = packh2(hh[0], hh[1]); hv.y = packh2(hh[2], hh[3]);
        lv.x = packh2(hl[0], hl[1]); lv.y = packh2(hl[2], hl[3]);
        *(uint2*)(Xh + ob + d + 64) = hv;
        *(uint2*)(Xl + ob + d + 64) = lv;
    }
}

// ---------------- gates ------------------------------------------------
__global__ void gates_kernel(const float* __restrict__ X,
                             const float* __restrict__ Wg1, const float* __restrict__ bg1,
                             const float* __restrict__ Wg2, const float* __restrict__ bg2,
                             float* __restrict__ G1, float* __restrict__ G2) {
    const int t    = blockIdx.x;
    const int warp = threadIdx.x >> 5;
    const int lane = threadIdx.x & 31;
    const float* x = X + (size_t)t * HID;
    float s0 = 0.f, s1 = 0.f, s2 = 0.f, s3 = 0.f;
    for (int k = lane; k < HID; k += 32) {
        const float xv = x[k];
        s0 = fmaf(xv, Wg1[k * NH + warp],     s0);
        s1 = fmaf(xv, Wg1[k * NH + warp + 8], s1);
        s2 = fmaf(xv, Wg2[k * NH + warp],     s2);
        s3 = fmaf(xv, Wg2[k * NH + warp + 8], s3);
    }
#pragma unroll
    for (int off = 16; off; off >>= 1) {
        s0 += __shfl_down_sync(0xffffffffu, s0, off);
        s1 += __shfl_down_sync(0xffffffffu, s1, off);
        s2 += __shfl_down_sync(0xffffffffu, s2, off);
        s3 += __shfl_down_sync(0xffffffffu, s3, off);
    }
    if (lane == 0) {
        G1[t * NH + warp]     = 1.f / (1.f + expf(-(s0 + bg1[warp])));
        G1[t * NH + warp + 8] = 1.f / (1.f + expf(-(s1 + bg1[warp + 8])));
        G2[t * NH + warp]     = 1.f / (1.f + expf(-(s2 + bg2[warp])));
        G2[t * NH + warp + 8] = 1.f / (1.f + expf(-(s3 + bg2[warp + 8])));
    }
}

// ---------------- HMMA flash attention, double-buffered K/V -----------------
// BM=128 q rows, BN=64 keys, 8 warps x 16 rows. 3-pass split-fp16 QK^T & PV.
#define BM 128
#define BN 64
#define QSTR 272   // bytes per Q/K row (136 halves)
#define VSTR 144   // bytes per V row (72 halves)
#define SQH_OFF 0
#define SQL_OFF 34816
#define SKV_BASE 69632          // 2 stages follow
#define KVSTG 71680             // per stage: KH 0 | KL 17408 | VH 34816 | VL 53248
#define SG2_OFF 212992          // 2 x 64 floats
#define SGAM_OFF 213504
#define SBET_OFF 214016
#define ATTN_SMEM 214528

__global__ __launch_bounds__(256, 1)
void attn_hmma(const __half* __restrict__ Qh, const __half* __restrict__ Ql,
               const __half* __restrict__ Kh, const __half* __restrict__ Kl,
               const __half* __restrict__ VTh, const __half* __restrict__ VTl,
               const float* __restrict__ G1, const float* __restrict__ G2,
               const float* __restrict__ gamma, const float* __restrict__ beta,
               __half* __restrict__ Oh, __half* __restrict__ Ol)
{
    extern __shared__ char smem[];
    const uint32_t sb = smem_u32(smem);
    float* sG2  = (float*)(smem + SG2_OFF);
    float* sGam = (float*)(smem + SGAM_OFF);
    float* sBet = (float*)(smem + SBET_OFF);

    const int tid = threadIdx.x, wid = tid >> 5, lane = tid & 31;
    const int qt = blockIdx.x, h = blockIdx.y, b = blockIdx.z;
    const int hk = h >> 2;
    const int q0 = qt * BM;
    const int tbase = b * S_LEN;
    const int wrow = wid * 16;
    const int c2 = 2 * (lane & 3);
    const size_t vrow0 = (size_t)(b * KVDIM + hk * HD) * S_LEN;

    if (tid < 128) { sGam[tid] = gamma[tid]; sBet[tid] = beta[tid]; }

    // Q tile (async, group 0)
    {
        const __half* gqh = Qh + (size_t)(tbase + q0) * QDIM + h * HD;
        const __half* gql = Ql + (size_t)(tbase + q0) * QDIM + h * HD;
#pragma unroll
        for (int t = 0; t < 8; t++) {
            const int idx = tid + t * 256;
            const int row = idx >> 4, cj = idx & 15;
            const uint32_t so = row * QSTR + cj * 16;
            cp16(sb + SQH_OFF + so, gqh + (size_t)row * QDIM + cj * 8);
            cp16(sb + SQL_OFF + so, gql + (size_t)row * QDIM + cj * 8);
        }
        CP_COMMIT();
    }

    auto load_kv = [&](int st, int j0) {
        const uint32_t kvb = sb + SKV_BASE + st * KVSTG;
        const __half* gkh = Kh + (size_t)(tbase + j0) * KVDIM + hk * HD;
        const __half* gkl = Kl + (size_t)(tbase + j0) * KVDIM + hk * HD;
#pragma unroll
        for (int t = 0; t < 4; t++) {
            const int idx = tid + t * 256;
            const int row = idx >> 4, cj = idx & 15;
            const uint32_t so = row * QSTR + cj * 16;
            cp16(kvb + so,         gkh + (size_t)row * KVDIM + cj * 8);
            cp16(kvb + 17408 + so, gkl + (size_t)row * KVDIM + cj * 8);
        }
#pragma unroll
        for (int t = 0; t < 4; t++) {
            const int idx = tid + t * 256;
            const int row = idx >> 3, cj = idx & 7;
            const uint32_t so = row * VSTR + cj * 16;
            cp16(kvb + 34816 + so, VTh + vrow0 + (size_t)row * S_LEN + j0 + cj * 8);
            cp16(kvb + 53248 + so, VTl + vrow0 + (size_t)row * S_LEN + j0 + cj * 8);
        }
        CP_COMMIT();
        if (tid < 64) sG2[st * 64 + tid] = G2[(size_t)(tbase + j0 + tid) * NH + h];
    };

    float m_i[2] = {-1e30f, -1e30f};
    float l_i[2] = {0.f, 0.f};
    float oacc[16][4];
#pragma unroll
    for (int nt = 0; nt < 16; nt++)
#pragma unroll
        for (int q = 0; q < 4; q++) oacc[nt][q] = 0.f;

    const float scale = 0.08838834764831845f;
    const uint32_t lrowQ = (lane & 15) * QSTR + (lane >> 4) * 16;
    const uint32_t lrowV = (lane & 15) * VSTR + (lane >> 4) * 16;
    const int ntiles = (q0 + BM) / BN;

    load_kv(0, 0);   // group 1

    for (int jt = 0; jt < ntiles; jt++) {
        const int j0 = jt * BN;
        if (jt + 1 < ntiles) { load_kv((jt + 1) & 1, j0 + BN); CP_WAIT1(); }
        else                 { CP_WAIT0(); }
        __syncthreads();

        const uint32_t kvb = sb + SKV_BASE + (jt & 1) * KVSTG;
        const float* g2c = sG2 + (jt & 1) * 64;

        if (j0 <= q0 + wrow + 15) {
            // ---- scores: S = Q K^T (3-pass split) ----
            float sacc[8][4];
#pragma unroll
            for (int nt = 0; nt < 8; nt++)
#pragma unroll
                for (int q = 0; q < 4; q++) sacc[nt][q] = 0.f;

#pragma unroll
            for (int kk = 0; kk < 8; kk++) {
                uint32_t ah[4], al[4];
                const uint32_t ra = sb + SQH_OFF + wrow * QSTR + lrowQ + kk * 32;
                ldsm4(ah, ra);
                ldsm4(al, ra + (SQL_OFF - SQH_OFF));
                uint32_t bh[8][2], bl[8][2];
#pragma unroll
                for (int n2 = 0; n2 < 4; n2++) {
                    const uint32_t rb = kvb + (16 * n2) * QSTR + lrowQ + kk * 32;
                    uint32_t t4[4];
                    ldsm4(t4, rb);
                    bh[2*n2][0] = t4[0]; bh[2*n2+1][0] = t4[1];
                    bh[2*n2][1] = t4[2]; bh[2*n2+1][1] = t4[3];
                    ldsm4(t4, rb + 17408);
                    bl[2*n2][0] = t4[0]; bl[2*n2+1][0] = t4[1];
                    bl[2*n2][1] = t4[2]; bl[2*n2+1][1] = t4[3];
                }
#pragma unroll
                for (int nt = 0; nt < 8; nt++) {
                    mma16816(sacc[nt], ah, bh[nt]);
                    mma16816(sacc[nt], ah, bl[nt]);
                    mma16816(sacc[nt], al, bh[nt]);
                }
            }

#pragma unroll
            for (int nt = 0; nt < 8; nt++)
#pragma unroll
                for (int q = 0; q < 4; q++) sacc[nt][q] *= scale;

            if (j0 + BN - 1 > q0 + wrow) {
                const int r0g = q0 + wrow + (lane >> 2);
#pragma unroll
                for (int nt = 0; nt < 8; nt++)
#pragma unroll
                    for (int q = 0; q < 4; q++) {
                        const int col = j0 + 8 * nt + c2 + (q & 1);
                        const int row = r0g + (q >> 1) * 8;
                        if (col > row) sacc[nt][q] = -1e30f;
                    }
            }

            // ---- online softmax ----
#pragma unroll
            for (int i = 0; i < 2; i++) {
                float rm = -1e30f;
#pragma unroll
                for (int nt = 0; nt < 8; nt++)
                    rm = fmaxf(rm, fmaxf(sacc[nt][2*i], sacc[nt][2*i+1]));
                rm = fmaxf(rm, __shfl_xor_sync(0xffffffffu, rm, 1));
                rm = fmaxf(rm, __shfl_xor_sync(0xffffffffu, rm, 2));
                const float mnew = fmaxf(m_i[i], rm);
                const float alpha = __expf(m_i[i] - mnew);
                float ls = 0.f;
#pragma unroll
                for (int nt = 0; nt < 8; nt++) {
                    sacc[nt][2*i]   = __expf(sacc[nt][2*i]   - mnew);
                    sacc[nt][2*i+1] = __expf(sacc[nt][2*i+1] - mnew);
                    ls += sacc[nt][2*i] + sacc[nt][2*i+1];
                }
                ls += __shfl_xor_sync(0xffffffffu, ls, 1);
                ls += __shfl_xor_sync(0xffffffffu, ls, 2);
                m_i[i] = mnew;
                l_i[i] = l_i[i] * alpha + ls;
#pragma unroll
                for (int nt = 0; nt < 16; nt++) {
                    oacc[nt][2*i]   *= alpha;
                    oacc[nt][2*i+1] *= alpha;
                }
            }

            // ---- gate by g2, split P, D-frag -> A-frag ----
            uint32_t pah[4][4], pal[4][4];
#pragma unroll
            for (int nt = 0; nt < 8; nt++) {
                const float g20 = g2c[8 * nt + c2];
                const float g21 = g2c[8 * nt + c2 + 1];
                const float p0 = sacc[nt][0] * g20;
                const float p1 = sacc[nt][1] * g21;
                const float p2 = sacc[nt][2] * g20;
                const float p3 = sacc[nt][3] * g21;
                const __half h0 = __float2half_rn(p0), h1 = __float2half_rn(p1);
                const __half h2 = __float2half_rn(p2), h3 = __float2half_rn(p3);
                const __half e0 = __float2half_rn(p0 - __half2float(h0));
                const __half e1 = __float2half_rn(p1 - __half2float(h1));
                const __half e2 = __float2half_rn(p2 - __half2float(h2));
                const __half e3 = __float2half_rn(p3 - __half2float(h3));
                const int t = nt >> 1;
                const int s = (nt & 1) * 2;
                pah[t][s]     = packh2(h0, h1);
                pah[t][s + 1] = packh2(h2, h3);
                pal[t][s]     = packh2(e0, e1);
                pal[t][s + 1] = packh2(e2, e3);
            }

            // ---- O += P V (3-pass split) ----
            const uint32_t vb = kvb + 34816;
#pragma unroll
            for (int nv2 = 0; nv2 < 8; nv2++) {
#pragma unroll
                for (int t = 0; t < 4; t++) {
                    uint32_t bvh[4], bvl[4];
                    const uint32_t rb = vb + (16 * nv2) * VSTR + lrowV + t * 32;
                    ldsm4(bvh, rb);
                    ldsm4(bvl, rb + 18432);
                    uint32_t be[2], bo[2], bel[2], bol[2];
                    be[0] = bvh[0]; be[1] = bvh[2]; bo[0] = bvh[1]; bo[1] = bvh[3];
                    bel[0] = bvl[0]; bel[1] = bvl[2]; bol[0] = bvl[1]; bol[1] = bvl[3];
                    mma16816(oacc[2*nv2],   pah[t], be);
                    mma16816(oacc[2*nv2],   pah[t], bel);
                    mma16816(oacc[2*nv2],   pal[t], be);
                    mma16816(oacc[2*nv2+1], pah[t], bo);
                    mma16816(oacc[2*nv2+1], pah[t], bol);
                    mma16816(oacc[2*nv2+1], pal[t], bo);
                }
            }
        }
        __syncthreads();
    }

    // ---- epilogue: /l, LayerNorm, *g1, emit fp16 hi/lo ----
#pragma unroll
    for (int i = 0; i < 2; i++) {
        const int row = q0 + wrow + (lane >> 2) + 8 * i;
        const float inv_l = 1.f / l_i[i];
        float x[32];
        float sum = 0.f;
#pragma unroll
        for (int nt = 0; nt < 16; nt++) {
            x[2*nt]   = oacc[nt][2*i]   * inv_l;
            x[2*nt+1] = oacc[nt][2*i+1] * inv_l;
            sum += x[2*nt] + x[2*nt+1];
        }
        sum += __shfl_xor_sync(0xffffffffu, sum, 1);
        sum += __shfl_xor_sync(0xffffffffu, sum, 2);
        const float mu = sum * (1.f / 128.f);
        float vs = 0.f;
#pragma unroll
        for (int j = 0; j < 32; j++) { const float d = x[j] - mu; vs += d * d; }
        vs += __shfl_xor_sync(0xffffffffu, vs, 1);
        vs += __shfl_xor_sync(0xffffffffu, vs, 2);
        const float rstd = rsqrtf(vs * (1.f / 128.f) + 1e-5f);
        const float g1v = G1[(size_t)(tbase + row) * NH + h];
        __half* oph = Oh + (size_t)(tbase + row) * QDIM + h * HD;
        __half* opl = Ol + (size_t)(tbase + row) * QDIM + h * HD;
#pragma unroll
        for (int nt = 0; nt < 16; nt++) {
            const int col = 8 * nt + c2;
            const float y0 = ((x[2*nt]   - mu) * rstd * sGam[col]     + sBet[col])     * g1v;
            const float y1 = ((x[2*nt+1] - mu) * rstd * sGam[col + 1] + sBet[col + 1]) * g1v;
            const __half h0 = __float2half_rn(y0), h1 = __float2half_rn(y1);
            const __half e0 = __float2half_rn(y0 - __half2float(h0));
            const __half e1 = __float2half_rn(y1 - __half2float(h1));
            *(uint32_t*)(oph + col) = packh2(h0, h1);
            *(uint32_t*)(opl + col) = packh2(e0, e1);
        }
    }
}

// ---------------- launch ---------------------------------------------------
extern "C" void kernel_launch(void* const* d_in, const int* in_sizes, int n_in,
                              void* d_out, int out_size) {
    const float* X     = (const float*)d_in[0];
    const int*   pos   = (const int*)d_in[1];
    const float* Wq    = (const float*)d_in[2];
    const float* Wk    = (const float*)d_in[3];
    const float* Wv    = (const float*)d_in[4];
    const float* Wo    = (const float*)d_in[5];
    const float* Wg1   = (const float*)d_in[6];
    const float* bg1   = (const float*)d_in[7];
    const float* Wg2   = (const float*)d_in[8];
    const float* bg2   = (const float*)d_in[9];
    const float* gamma = (const float*)d_in[10];
    const float* beta  = (const float*)d_in[11];
    float* out = (float*)d_out;

    void *pQ, *pK, *pV, *pG1, *pG2, *pRT;
    void *pXh, *pXl, *pOh, *pOl, *pWh, *pWl, *pWoh, *pWol;
    void *pQh, *pQl, *pKh, *pKl, *pVTh, *pVTl;
    cudaGetSymbolAddress(&pQ,  g_Q);
    cudaGetSymbolAddress(&pK,  g_K);
    cudaGetSymbolAddress(&pV,  g_V);
    cudaGetSymbolAddress(&pG1, g_G1);
    cudaGetSymbolAddress(&pG2, g_G2);
    cudaGetSymbolAddress(&pRT, g_RT);
    cudaGetSymbolAddress(&pXh, g_Xh);
    cudaGetSymbolAddress(&pXl, g_Xl);
    cudaGetSymbolAddress(&pOh, g_Oh);
    cudaGetSymbolAddress(&pOl, g_Ol);
    cudaGetSymbolAddress(&pWh, g_WqkvTh);
    cudaGetSymbolAddress(&pWl, g_WqkvTl);
    cudaGetSymbolAddress(&pWoh, g_WoTh);
    cudaGetSymbolAddress(&pWol, g_WoTl);
    cudaGetSymbolAddress(&pQh, g_Qh);
    cudaGetSymbolAddress(&pQl, g_Ql);
    cudaGetSymbolAddress(&pKh, g_Kh);
    cudaGetSymbolAddress(&pKl, g_Kl);
    cudaGetSymbolAddress(&pVTh, g_VTh);
    cudaGetSymbolAddress(&pVTl, g_VTl);

    float* Qp  = (float*)pQ;
    float* Kp  = (float*)pK;
    float* Vp  = (float*)pV;
    float* G1p = (float*)pG1;
    float* G2p = (float*)pG2;
    float* RTp = (float*)pRT;

    // prep
    split_kernel<<<512, 256>>>((const float4*)X, (uint2*)pXh, (uint2*)pXl,
                               TOK * HID / 4);
    rope_table<<<(S_LEN * 64 + 255) / 256, 256>>>(pos, RTp);
    wqkv_tsplit<<<dim3(HID / 32, NQKV / 32), dim3(32, 8)>>>(
        Wq, Wk, Wv, (__half*)pWh, (__half*)pWl);
    wo_tsplit<<<dim3(QDIM / 32, HID / 32), dim3(32, 8)>>>(
        Wo, (__half*)pWoh, (__half*)pWol);
    gates_kernel<<<TOK, 256>>>(X, Wg1, bg1, Wg2, bg2, G1p, G2p);

    // QKV projection (HMMA)
    cudaFuncSetAttribute(gemm_qkv_tc, cudaFuncAttributeMaxDynamicSharedMemorySize,
                         GEMM_SMEM);
    gemm_qkv_tc<<<dim3(NQKV / 128, TOK / 128), 256, GEMM_SMEM>>>(
        (const __half*)pXh, (const __half*)pXl,
        (const __half*)pWh, (const __half*)pWl, Qp, Kp, Vp);

    // fused RoPE + split for Q and K; transpose+split V
    rope_split<<<1024, 256>>>(Qp, RTp, (__half*)pQh, (__half*)pQl, NH);
    rope_split<<<256, 256>>>(Kp, RTp, (__half*)pKh, (__half*)pKl, NKV);
    vt_tsplit<<<dim3(KVDIM / 32, S_LEN / 32, BATCH), dim3(32, 8)>>>(
        Vp, (__half*)pVTh, (__half*)pVTl);

    // HMMA flash attention, double-buffered K/V
    cudaFuncSetAttribute(attn_hmma, cudaFuncAttributeMaxDynamicSharedMemorySize,
                         ATTN_SMEM);
    attn_hmma<<<dim3(S_LEN / BM, NH, BATCH), 256, ATTN_SMEM>>>(
        (const __half*)pQh, (const __half*)pQl,
        (const __half*)pKh, (const __half*)pKl,
        (const __half*)pVTh, (const __half*)pVTl,
        G1p, G2p, gamma, beta, (__half*)pOh, (__half*)pOl);

    // output projection (HMMA)
    cudaFuncSetAttribute(gemm_o_tc, cudaFuncAttributeMaxDynamicSharedMemorySize,
                         GEMM_SMEM);
    gemm_o_tc<<<dim3(HID / 128, TOK / 128), 256, GEMM_SMEM>>>(
        (const __half*)pOh, (const __half*)pOl,
        (const __half*)pWoh, (const __half*)pWol, out);
}

// round 15
// speedup vs baseline: 3.5145x; 1.0430x over previous
#include <cuda_runtime.h>
#include <cuda_fp16.h>
#include <math.h>
#include <cstdint>

#define S_LEN 2048
#define BATCH 2
#define TOK   (BATCH * S_LEN)   // 4096
#define HID   2048
#define NH    16
#define NKV   4
#define HD    128
#define QDIM  (NH * HD)         // 2048
#define KVDIM (NKV * HD)        // 512
#define NQKV  (QDIM + 2 * KVDIM) // 3072

// ---------------- scratch (static device arrays; no allocs) ----------------
__device__ float g_Q[TOK * QDIM];
__device__ float g_K[TOK * KVDIM];
__device__ float g_V[TOK * KVDIM];
__device__ float g_G1[TOK * NH];
__device__ float g_G2[TOK * NH];
__device__ float g_RT[S_LEN * 128];
__device__ __half g_Xh[TOK * HID];
__device__ __half g_Xl[TOK * HID];
__device__ __half g_Oh[TOK * QDIM];
__device__ __half g_Ol[TOK * QDIM];
__device__ __half g_Qh[TOK * QDIM];
__device__ __half g_Ql[TOK * QDIM];
__device__ __half g_Kh[TOK * KVDIM];
__device__ __half g_Kl[TOK * KVDIM];
__device__ __half g_VTh[BATCH * KVDIM * S_LEN];  // [b*512 + c][s]
__device__ __half g_VTl[BATCH * KVDIM * S_LEN];
__device__ __half g_WqkvTh[NQKV * HID];
__device__ __half g_WqkvTl[NQKV * HID];
__device__ __half g_WoTh[HID * QDIM];
__device__ __half g_WoTl[HID * QDIM];

// ---------------- PTX helpers (baseline ISA only) ---------------------------
__device__ __forceinline__ uint32_t smem_u32(const void* p) {
    uint32_t a;
    asm("{ .reg .u64 t; cvta.to.shared.u64 t, %1; cvt.u32.u64 %0, t; }"
        : "=r"(a) : "l"(p));
    return a;
}
__device__ __forceinline__ void cp16(uint32_t s, const void* g) {
    asm volatile("cp.async.cg.shared.global [%0], [%1], 16;" :: "r"(s), "l"(g));
}
#define CP_COMMIT() asm volatile("cp.async.commit_group;" ::: "memory")
#define CP_WAIT1()  asm volatile("cp.async.wait_group 1;" ::: "memory")
#define CP_WAIT0()  asm volatile("cp.async.wait_group 0;" ::: "memory")

__device__ __forceinline__ void ldsm4(uint32_t* r, uint32_t a) {
    asm volatile("ldmatrix.sync.aligned.m8n8.x4.shared.b16 {%0,%1,%2,%3}, [%4];"
                 : "=r"(r[0]), "=r"(r[1]), "=r"(r[2]), "=r"(r[3]) : "r"(a));
}
__device__ __forceinline__ void mma16816(float* d, const uint32_t* a, const uint32_t* b) {
    asm volatile("mma.sync.aligned.m16n8k16.row.col.f32.f16.f16.f32 "
                 "{%0,%1,%2,%3}, {%4,%5,%6,%7}, {%8,%9}, {%0,%1,%2,%3};"
                 : "+f"(d[0]), "+f"(d[1]), "+f"(d[2]), "+f"(d[3])
                 : "r"(a[0]), "r"(a[1]), "r"(a[2]), "r"(a[3]), "r"(b[0]), "r"(b[1]));
}
__device__ __forceinline__ uint32_t packh2(__half a, __half b) {
    __half2 h = __halves2half2(a, b);
    return *(uint32_t*)&h;
}

// ---------------- split: fp32 -> (fp16 hi, fp16 lo) ------------------------
__global__ void split_kernel(const float4* __restrict__ in,
                             uint2* __restrict__ hi, uint2* __restrict__ lo, int n4) {
    for (int i = blockIdx.x * blockDim.x + threadIdx.x; i < n4;
         i += gridDim.x * blockDim.x) {
        const float4 v = in[i];
        const __half h0 = __float2half_rn(v.x);
        const __half h1 = __float2half_rn(v.y);
        const __half h2 = __float2half_rn(v.z);
        const __half h3 = __float2half_rn(v.w);
        const __half l0 = __float2half_rn(v.x - __half2float(h0));
        const __half l1 = __float2half_rn(v.y - __half2float(h1));
        const __half l2 = __float2half_rn(v.z - __half2float(h2));
        const __half l3 = __float2half_rn(v.w - __half2float(h3));
        uint2 hw, lw;
        hw.x = packh2(h0, h1); hw.y = packh2(h2, h3);
        lw.x = packh2(l0, l1); lw.y = packh2(l2, l3);
        hi[i] = hw;
        lo[i] = lw;
    }
}

// ---------------- weight transpose + split ---------------------------------
__global__ void wqkv_tsplit(const float* __restrict__ Wq, const float* __restrict__ Wk,
                            const float* __restrict__ Wv,
                            __half* __restrict__ WTh, __half* __restrict__ WTl) {
    __shared__ float t[32][33];
    const int k0 = blockIdx.x * 32;
    const int n0 = blockIdx.y * 32;
    const float* src; int srcN, ncol;
    if (n0 < QDIM)              { src = Wq; srcN = QDIM;  ncol = n0; }
    else if (n0 < QDIM + KVDIM) { src = Wk; srcN = KVDIM; ncol = n0 - QDIM; }
    else                        { src = Wv; srcN = KVDIM; ncol = n0 - QDIM - KVDIM; }
    const int tx = threadIdx.x, ty = threadIdx.y;
#pragma unroll
    for (int j = 0; j < 32; j += 8)
        t[ty + j][tx] = src[(size_t)(k0 + ty + j) * srcN + ncol + tx];
    __syncthreads();
#pragma unroll
    for (int j = 0; j < 32; j += 8) {
        const float v = t[tx][ty + j];
        const __half h = __float2half_rn(v);
        const __half l = __float2half_rn(v - __half2float(h));
        const size_t o = (size_t)(n0 + ty + j) * HID + k0 + tx;
        WTh[o] = h;
        WTl[o] = l;
    }
}

__global__ void wo_tsplit(const float* __restrict__ Wo,
                          __half* __restrict__ WTh, __half* __restrict__ WTl) {
    __shared__ float t[32][33];
    const int k0 = blockIdx.x * 32;
    const int n0 = blockIdx.y * 32;
    const int tx = threadIdx.x, ty = threadIdx.y;
#pragma unroll
    for (int j = 0; j < 32; j += 8)
        t[ty + j][tx] = Wo[(size_t)(k0 + ty + j) * HID + n0 + tx];
    __syncthreads();
#pragma unroll
    for (int j = 0; j < 32; j += 8) {
        const float v = t[tx][ty + j];
        const __half h = __float2half_rn(v);
        const __half l = __float2half_rn(v - __half2float(h));
        const size_t o = (size_t)(n0 + ty + j) * QDIM + k0 + tx;
        WTh[o] = h;
        WTl[o] = l;
    }
}

// ---------------- V transpose + split --------------------------------------
__global__ void vt_tsplit(const float* __restrict__ V,
                          __half* __restrict__ VTh, __half* __restrict__ VTl) {
    __shared__ float t[32][33];
    const int c0 = blockIdx.x * 32;
    const int s0 = blockIdx.y * 32;
    const int b  = blockIdx.z;
    const int tx = threadIdx.x, ty = threadIdx.y;
#pragma unroll
    for (int j = 0; j < 32; j += 8)
        t[ty + j][tx] = V[(size_t)(b * S_LEN + s0 + ty + j) * KVDIM + c0 + tx];
    __syncthreads();
#pragma unroll
    for (int j = 0; j < 32; j += 8) {
        const float v = t[tx][ty + j];
        const __half h = __float2half_rn(v);
        const __half l = __float2half_rn(v - __half2float(h));
        const size_t o = (size_t)(b * KVDIM + c0 + ty + j) * S_LEN + s0 + tx;
        VTh[o] = h;
        VTl[o] = l;
    }
}

// ---------------- HMMA split-fp16 GEMM (validated R8/R9, 3-pass) ------------
#define TILE_B   10240
#define GSTAGE_B (4 * TILE_B)
#define GEMM_SMEM (2 * GSTAGE_B)

__device__ __forceinline__ void gemm_hmma_tile(
    const __half* __restrict__ Ah, const __half* __restrict__ Al,
    const __half* __restrict__ Bh, const __half* __restrict__ Bl,
    float* __restrict__ C, int ldc, int K, int brow, int bn, int bcolC)
{
    extern __shared__ char smem[];
    const uint32_t sb = smem_u32(smem);

    const int tid  = threadIdx.x;
    const int wid  = tid >> 5;
    const int lane = tid & 31;
    const int wm = (wid & 3) * 32;
    const int wn = (wid >> 2) * 64;

    float acc[2][8][4];
#pragma unroll
    for (int mt = 0; mt < 2; mt++)
#pragma unroll
        for (int nt = 0; nt < 8; nt++)
#pragma unroll
            for (int q = 0; q < 4; q++) acc[mt][nt][q] = 0.f;

    const size_t rowB = (size_t)K * 2;
    const char* gAh = (const char*)(Ah + (size_t)brow * K);
    const char* gAl = (const char*)(Al + (size_t)brow * K);
    const char* gBh = (const char*)(Bh + (size_t)bn * K);
    const char* gBl = (const char*)(Bl + (size_t)bn * K);

    const int r  = tid >> 1;
    const int j0 = (tid & 1) * 2;
    const uint32_t sdst = (uint32_t)(r * 80);
    const size_t gsrc_row = (size_t)r * rowB;

    auto load_stage = [&](int st, int c) {
        const size_t kb = (size_t)c * 64;
        const uint32_t s0 = sb + st * GSTAGE_B + sdst;
#pragma unroll
        for (int jj = 0; jj < 2; jj++) {
            const int j = j0 + jj;
            const uint32_t so = s0 + j * 16;
            const size_t go = gsrc_row + kb + j * 16;
            cp16(so,              gAh + go);
            cp16(so + TILE_B,     gAl + go);
            cp16(so + 2 * TILE_B, gBh + go);
            cp16(so + 3 * TILE_B, gBl + go);
        }
        CP_COMMIT();
    };

    const int nchunk = K / 32;
    load_stage(0, 0);
    for (int c = 0; c < nchunk; c++) {
        if (c + 1 < nchunk) { load_stage((c + 1) & 1, c + 1); CP_WAIT1(); }
        else                { CP_WAIT0(); }
        __syncthreads();

        const uint32_t st_base = sb + (c & 1) * GSTAGE_B;
        const uint32_t lrow = (uint32_t)((lane & 15) * 80 + ((lane >> 4) * 16));
#pragma unroll
        for (int kk = 0; kk < 2; kk++) {
            const uint32_t kb = kk * 32;
            uint32_t ah[2][4], al[2][4], bh[8][2], bl[8][2];
#pragma unroll
            for (int mt = 0; mt < 2; mt++) {
                const uint32_t ra = st_base + (wm + 16 * mt) * 80 + lrow + kb;
                ldsm4(ah[mt], ra);
                ldsm4(al[mt], ra + TILE_B);
            }
#pragma unroll
            for (int nt2 = 0; nt2 < 4; nt2++) {
                const uint32_t rb = st_base + 2 * TILE_B + (wn + 16 * nt2) * 80 + lrow + kb;
                uint32_t t[4];
                ldsm4(t, rb);
                bh[2 * nt2][0] = t[0]; bh[2 * nt2 + 1][0] = t[1];
                bh[2 * nt2][1] = t[2]; bh[2 * nt2 + 1][1] = t[3];
                ldsm4(t, rb + TILE_B);
                bl[2 * nt2][0] = t[0]; bl[2 * nt2 + 1][0] = t[1];
                bl[2 * nt2][1] = t[2]; bl[2 * nt2 + 1][1] = t[3];
            }
#pragma unroll
            for (int mt = 0; mt < 2; mt++)
#pragma unroll
                for (int nt = 0; nt < 8; nt++) {
                    mma16816(acc[mt][nt], ah[mt], bh[nt]);
                    mma16816(acc[mt][nt], ah[mt], bl[nt]);
                    mma16816(acc[mt][nt], al[mt], bh[nt]);
                }
        }
        __syncthreads();
    }

#pragma unroll
    for (int mt = 0; mt < 2; mt++) {
        const int r0 = brow + wm + 16 * mt + (lane >> 2);
#pragma unroll
        for (int nt = 0; nt < 8; nt++) {
            const int cc = bcolC + wn + 8 * nt + 2 * (lane & 3);
            float2* p0 = (float2*)(C + (size_t)r0 * ldc + cc);
            *p0 = make_float2(acc[mt][nt][0], acc[mt][nt][1]);
            float2* p1 = (float2*)(C + (size_t)(r0 + 8) * ldc + cc);
            *p1 = make_float2(acc[mt][nt][2], acc[mt][nt][3]);
        }
    }
}

__global__ __launch_bounds__(256)
void gemm_qkv_tc(const __half* Ah, const __half* Al,
                 const __half* Bh, const __half* Bl,
                 float* Q, float* Kd, float* Vd) {
    const int ct = blockIdx.x;
    float* C; int ldc, bcolC;
    if (ct < 16)      { C = Q;  ldc = QDIM;  bcolC = ct * 128; }
    else if (ct < 20) { C = Kd; ldc = KVDIM; bcolC = (ct - 16) * 128; }
    else              { C = Vd; ldc = KVDIM; bcolC = (ct - 20) * 128; }
    gemm_hmma_tile(Ah, Al, Bh, Bl, C, ldc, HID, blockIdx.y * 128, ct * 128, bcolC);
}

__global__ __launch_bounds__(256)
void gemm_o_tc(const __half* Ah, const __half* Al,
               const __half* Bh, const __half* Bl, float* C) {
    gemm_hmma_tile(Ah, Al, Bh, Bl, C, HID, QDIM,
                   blockIdx.y * 128, blockIdx.x * 128, blockIdx.x * 128);
}

// ---------------- RoPE table ------------------------------------------------
__global__ void rope_table(const int* __restrict__ pos_ids, float* __restrict__ tab) {
    const int i = blockIdx.x * blockDim.x + threadIdx.x;
    if (i >= S_LEN * 64) return;
    const int s = i >> 6, d = i & 63;
    const int pos = pos_ids[s];
    const double invf = exp(-(double)d * (9.210340371976184 / 64.0));
    const double ang  = fmod((double)pos * invf, 6.283185307179586);
    float sn, cs;
    sincosf((float)ang, &sn, &cs);
    tab[s * 128 + d]      = cs;
    tab[s * 128 + 64 + d] = sn;
}

// ---------------- fused rope + split: fp32 X -> fp16 hi/lo ------------------
__global__ void rope_split(const float* __restrict__ X, const float* __restrict__ tab,
                           __half* __restrict__ Xh, __half* __restrict__ Xl,
                           int nheads) {
    const int total = TOK * nheads * 16;   // 4 pairs per thread
    for (int idx = blockIdx.x * blockDim.x + threadIdx.x; idx < total;
         idx += gridDim.x * blockDim.x) {
        const int d4   = idx & 15;
        const int rest = idx >> 4;
        const int h    = rest % nheads;
        const int t    = rest / nheads;
        const int s    = t & (S_LEN - 1);
        const int d    = d4 * 4;
        const float4 c4 = *(const float4*)&tab[s * 128 + d];
        const float4 s4 = *(const float4*)&tab[s * 128 + 64 + d];
        const float* base = X + (size_t)t * (nheads * HD) + h * HD;
        const float4 x0 = *(const float4*)&base[d];
        const float4 x1 = *(const float4*)&base[d + 64];
        float y0[4], y1[4];
        y0[0] = x0.x * c4.x - x1.x * s4.x;  y1[0] = x1.x * c4.x + x0.x * s4.x;
        y0[1] = x0.y * c4.y - x1.y * s4.y;  y1[1] = x1.y * c4.y + x0.y * s4.y;
        y0[2] = x0.z * c4.z - x1.z * s4.z;  y1[2] = x1.z * c4.z + x0.z * s4.z;
        y0[3] = x0.w * c4.w - x1.w * s4.w;  y1[3] = x1.w * c4.w + x0.w * s4.w;
        const size_t ob = (size_t)t * (nheads * HD) + h * HD;
        uint2 hv, lv;
        __half hh[4], hl[4];
#pragma unroll
        for (int j = 0; j < 4; j++) {
            hh[j] = __float2half_rn(y0[j]);
            hl[j] = __float2half_rn(y0[j] - __half2float(hh[j]));
        }
        hv.x = packh2(hh[0], hh[1]); hv.y = packh2(hh[2], hh[3]);
        lv.x = packh2(hl[0], hl[1]); lv.y = packh2(hl[2], hl[3]);
        *(uint2*)(Xh + ob + d) = hv;
        *(uint2*)(Xl + ob + d) = lv;
#pragma unroll
        for (int j = 0; j < 4; j++) {
            hh[j] = __float2half_rn(y1[j]);
            hl[j] = __float2half_rn(y1[j] - __half2float(hh[j]));
        }
        hv.x = packh2(hh[0], hh[1]); hv.y = packh2(hh[2], hh[3]);
        lv.x = packh2(hl[0], hl[1]); lv.y = packh2(hl[2], hl[3]);
        *(uint2*)(Xh + ob + d + 64) = hv;
        *(uint2*)(Xl + ob + d + 64) = lv;
    }
}

// ---------------- gates ------------------------------------------------
__global__ void gates_kernel(const float* __restrict__ X,
                             const float* __restrict__ Wg1, const float* __restrict__ bg1,
                             const float* __restrict__ Wg2, const float* __restrict__ bg2,
                             float* __restrict__ G1, float* __restrict__ G2) {
    const int t    = blockIdx.x;
    const int warp = threadIdx.x >> 5;
    const int lane = threadIdx.x & 31;
    const float* x = X + (size_t)t * HID;
    float s0 = 0.f, s1 = 0.f, s2 = 0.f, s3 = 0.f;
    for (int k = lane; k < HID; k += 32) {
        const float xv = x[k];
        s0 = fmaf(xv, Wg1[k * NH + warp],     s0);
        s1 = fmaf(xv, Wg1[k * NH + warp + 8], s1);
        s2 = fmaf(xv, Wg2[k * NH + warp],     s2);
        s3 = fmaf(xv, Wg2[k * NH + warp + 8], s3);
    }
#pragma unroll
    for (int off = 16; off; off >>= 1) {
        s0 += __shfl_down_sync(0xffffffffu, s0, off);
        s1 += __shfl_down_sync(0xffffffffu, s1, off);
        s2 += __shfl_down_sync(0xffffffffu, s2, off);
        s3 += __shfl_down_sync(0xffffffffu, s3, off);
    }
    if (lane == 0) {
        G1[t * NH + warp]     = 1.f / (1.f + expf(-(s0 + bg1[warp])));
        G1[t * NH + warp + 8] = 1.f / (1.f + expf(-(s1 + bg1[warp + 8])));
        G2[t * NH + warp]     = 1.f / (1.f + expf(-(s2 + bg2[warp])));
        G2[t * NH + warp + 8] = 1.f / (1.f + expf(-(s3 + bg2[warp + 8])));
    }
}

// ---------------- HMMA flash attention, 2-pass split ------------------------
// BM=128 q rows, BN=64 keys, 8 warps x 16 rows.
// QK^T: Qh*Kh + Qh*Kl (Ql dropped). PV: Ph*Vh + Ph*Vl (Pl dropped).
#define BM 128
#define BN 64
#define QSTR 272   // bytes per Q/K row (136 halves)
#define VSTR 144   // bytes per V row (72 halves)
#define SQH_OFF 0
#define SKV_BASE 34816          // 2 stages follow (Ql region removed)
#define KVSTG 71680             // per stage: KH 0 | KL 17408 | VH 34816 | VL 53248
#define SG2_OFF 178176          // 2 x 64 floats
#define SGAM_OFF 178688
#define SBET_OFF 179200
#define ATTN_SMEM 179712

__global__ __launch_bounds__(256, 1)
void attn_hmma(const __half* __restrict__ Qh,
               const __half* __restrict__ Kh, const __half* __restrict__ Kl,
               const __half* __restrict__ VTh, const __half* __restrict__ VTl,
               const float* __restrict__ G1, const float* __restrict__ G2,
               const float* __restrict__ gamma, const float* __restrict__ beta,
               __half* __restrict__ Oh, __half* __restrict__ Ol)
{
    extern __shared__ char smem[];
    const uint32_t sb = smem_u32(smem);
    float* sG2  = (float*)(smem + SG2_OFF);
    float* sGam = (float*)(smem + SGAM_OFF);
    float* sBet = (float*)(smem + SBET_OFF);

    const int tid = threadIdx.x, wid = tid >> 5, lane = tid & 31;
    const int qt = blockIdx.x, h = blockIdx.y, b = blockIdx.z;
    const int hk = h >> 2;
    const int q0 = qt * BM;
    const int tbase = b * S_LEN;
    const int wrow = wid * 16;
    const int c2 = 2 * (lane & 3);
    const size_t vrow0 = (size_t)(b * KVDIM + hk * HD) * S_LEN;

    if (tid < 128) { sGam[tid] = gamma[tid]; sBet[tid] = beta[tid]; }

    // Q tile (hi only; async, group 0)
    {
        const __half* gqh = Qh + (size_t)(tbase + q0) * QDIM + h * HD;
#pragma unroll
        for (int t = 0; t < 8; t++) {
            const int idx = tid + t * 256;
            const int row = idx >> 4, cj = idx & 15;
            const uint32_t so = row * QSTR + cj * 16;
            cp16(sb + SQH_OFF + so, gqh + (size_t)row * QDIM + cj * 8);
        }
        CP_COMMIT();
    }

    auto load_kv = [&](int st, int j0) {
        const uint32_t kvb = sb + SKV_BASE + st * KVSTG;
        const __half* gkh = Kh + (size_t)(tbase + j0) * KVDIM + hk * HD;
        const __half* gkl = Kl + (size_t)(tbase + j0) * KVDIM + hk * HD;
#pragma unroll
        for (int t = 0; t < 4; t++) {
            const int idx = tid + t * 256;
            const int row = idx >> 4, cj = idx & 15;
            const uint32_t so = row * QSTR + cj * 16;
            cp16(kvb + so,         gkh + (size_t)row * KVDIM + cj * 8);
            cp16(kvb + 17408 + so, gkl + (size_t)row * KVDIM + cj * 8);
        }
#pragma unroll
        for (int t = 0; t < 4; t++) {
            const int idx = tid + t * 256;
            const int row = idx >> 3, cj = idx & 7;
            const uint32_t so = row * VSTR + cj * 16;
            cp16(kvb + 34816 + so, VTh + vrow0 + (size_t)row * S_LEN + j0 + cj * 8);
            cp16(kvb + 53248 + so, VTl + vrow0 + (size_t)row * S_LEN + j0 + cj * 8);
        }
        CP_COMMIT();
        if (tid < 64) sG2[st * 64 + tid] = G2[(size_t)(tbase + j0 + tid) * NH + h];
    };

    float m_i[2] = {-1e30f, -1e30f};
    float l_i[2] = {0.f, 0.f};
    float oacc[16][4];
#pragma unroll
    for (int nt = 0; nt < 16; nt++)
#pragma unroll
        for (int q = 0; q < 4; q++) oacc[nt][q] = 0.f;

    const float scale = 0.08838834764831845f;
    const uint32_t lrowQ = (lane & 15) * QSTR + (lane >> 4) * 16;
    const uint32_t lrowV = (lane & 15) * VSTR + (lane >> 4) * 16;
    const int ntiles = (q0 + BM) / BN;

    load_kv(0, 0);   // group 1

    for (int jt = 0; jt < ntiles; jt++) {
        const int j0 = jt * BN;
        if (jt + 1 < ntiles) { load_kv((jt + 1) & 1, j0 + BN); CP_WAIT1(); }
        else                 { CP_WAIT0(); }
        __syncthreads();

        const uint32_t kvb = sb + SKV_BASE + (jt & 1) * KVSTG;
        const float* g2c = sG2 + (jt & 1) * 64;

        if (j0 <= q0 + wrow + 15) {
            // ---- scores: S = Qh*Kh + Qh*Kl (2-pass) ----
            float sacc[8][4];
#pragma unroll
            for (int nt = 0; nt < 8; nt++)
#pragma unroll
                for (int q = 0; q < 4; q++) sacc[nt][q] = 0.f;

#pragma unroll
            for (int kk = 0; kk < 8; kk++) {
                uint32_t ah[4];
                const uint32_t ra = sb + SQH_OFF + wrow * QSTR + lrowQ + kk * 32;
                ldsm4(ah, ra);
                uint32_t bh[8][2], bl[8][2];
#pragma unroll
                for (int n2 = 0; n2 < 4; n2++) {
                    const uint32_t rb = kvb + (16 * n2) * QSTR + lrowQ + kk * 32;
                    uint32_t t4[4];
                    ldsm4(t4, rb);
                    bh[2*n2][0] = t4[0]; bh[2*n2+1][0] = t4[1];
                    bh[2*n2][1] = t4[2]; bh[2*n2+1][1] = t4[3];
                    ldsm4(t4, rb + 17408);
                    bl[2*n2][0] = t4[0]; bl[2*n2+1][0] = t4[1];
                    bl[2*n2][1] = t4[2]; bl[2*n2+1][1] = t4[3];
                }
#pragma unroll
                for (int nt = 0; nt < 8; nt++) {
                    mma16816(sacc[nt], ah, bh[nt]);
                    mma16816(sacc[nt], ah, bl[nt]);
                }
            }

#pragma unroll
            for (int nt = 0; nt < 8; nt++)
#pragma unroll
                for (int q = 0; q < 4; q++) sacc[nt][q] *= scale;

            if (j0 + BN - 1 > q0 + wrow) {
                const int r0g = q0 + wrow + (lane >> 2);
#pragma unroll
                for (int nt = 0; nt < 8; nt++)
#pragma unroll
                    for (int q = 0; q < 4; q++) {
                        const int col = j0 + 8 * nt + c2 + (q & 1);
                        const int row = r0g + (q >> 1) * 8;
                        if (col > row) sacc[nt][q] = -1e30f;
                    }
            }

            // ---- online softmax ----
#pragma unroll
            for (int i = 0; i < 2; i++) {
                float rm = -1e30f;
#pragma unroll
                for (int nt = 0; nt < 8; nt++)
                    rm = fmaxf(rm, fmaxf(sacc[nt][2*i], sacc[nt][2*i+1]));
                rm = fmaxf(rm, __shfl_xor_sync(0xffffffffu, rm, 1));
                rm = fmaxf(rm, __shfl_xor_sync(0xffffffffu, rm, 2));
                const float mnew = fmaxf(m_i[i], rm);
                const float alpha = __expf(m_i[i] - mnew);
                float ls = 0.f;
#pragma unroll
                for (int nt = 0; nt < 8; nt++) {
                    sacc[nt][2*i]   = __expf(sacc[nt][2*i]   - mnew);
                    sacc[nt][2*i+1] = __expf(sacc[nt][2*i+1] - mnew);
                    ls += sacc[nt][2*i] + sacc[nt][2*i+1];
                }
                ls += __shfl_xor_sync(0xffffffffu, ls, 1);
                ls += __shfl_xor_sync(0xffffffffu, ls, 2);
                m_i[i] = mnew;
                l_i[i] = l_i[i] * alpha + ls;
#pragma unroll
                for (int nt = 0; nt < 16; nt++) {
                    oacc[nt][2*i]   *= alpha;
                    oacc[nt][2*i+1] *= alpha;
                }
            }

            // ---- gate by g2, P hi only, D-frag -> A-frag ----
            uint32_t pah[4][4];
#pragma unroll
            for (int nt = 0; nt < 8; nt++) {
                const float g20 = g2c[8 * nt + c2];
                const float g21 = g2c[8 * nt + c2 + 1];
                const __half h0 = __float2half_rn(sacc[nt][0] * g20);
                const __half h1 = __float2half_rn(sacc[nt][1] * g21);
                const __half h2 = __float2half_rn(sacc[nt][2] * g20);
                const __half h3 = __float2half_rn(sacc[nt][3] * g21);
                const int t = nt >> 1;
                const int s = (nt & 1) * 2;
                pah[t][s]     = packh2(h0, h1);
                pah[t][s + 1] = packh2(h2, h3);
            }

            // ---- O += Ph*Vh + Ph*Vl (2-pass) ----
            const uint32_t vb = kvb + 34816;
#pragma unroll
            for (int nv2 = 0; nv2 < 8; nv2++) {
#pragma unroll
                for (int t = 0; t < 4; t++) {
                    uint32_t bvh[4], bvl[4];
                    const uint32_t rb = vb + (16 * nv2) * VSTR + lrowV + t * 32;
                    ldsm4(bvh, rb);
                    ldsm4(bvl, rb + 18432);
                    uint32_t be[2], bo[2], bel[2], bol[2];
                    be[0] = bvh[0]; be[1] = bvh[2]; bo[0] = bvh[1]; bo[1] = bvh[3];
                    bel[0] = bvl[0]; bel[1] = bvl[2]; bol[0] = bvl[1]; bol[1] = bvl[3];
                    mma16816(oacc[2*nv2],   pah[t], be);
                    mma16816(oacc[2*nv2],   pah[t], bel);
                    mma16816(oacc[2*nv2+1], pah[t], bo);
                    mma16816(oacc[2*nv2+1], pah[t], bol);
                }
            }
        }
        __syncthreads();
    }

    // ---- epilogue: /l, LayerNorm, *g1, emit fp16 hi/lo ----
#pragma unroll
    for (int i = 0; i < 2; i++) {
        const int row = q0 + wrow + (lane >> 2) + 8 * i;
        const float inv_l = 1.f / l_i[i];
        float x[32];
        float sum = 0.f;
#pragma unroll
        for (int nt = 0; nt < 16; nt++) {
            x[2*nt]   = oacc[nt][2*i]   * inv_l;
            x[2*nt+1] = oacc[nt][2*i+1] * inv_l;
            sum += x[2*nt] + x[2*nt+1];
        }
        sum += __shfl_xor_sync(0xffffffffu, sum, 1);
        sum += __shfl_xor_sync(0xffffffffu, sum, 2);
        const float mu = sum * (1.f / 128.f);
        float vs = 0.f;
#pragma unroll
        for (int j = 0; j < 32; j++) { const float d = x[j] - mu; vs += d * d; }
        vs += __shfl_xor_sync(0xffffffffu, vs, 1);
        vs += __shfl_xor_sync(0xffffffffu, vs, 2);
        const float rstd = rsqrtf(vs * (1.f / 128.f) + 1e-5f);
        const float g1v = G1[(size_t)(tbase + row) * NH + h];
        __half* oph = Oh + (size_t)(tbase + row) * QDIM + h * HD;
        __half* opl = Ol + (size_t)(tbase + row) * QDIM + h * HD;
#pragma unroll
        for (int nt = 0; nt < 16; nt++) {
            const int col = 8 * nt + c2;
            const float y0 = ((x[2*nt]   - mu) * rstd * sGam[col]     + sBet[col])     * g1v;
            const float y1 = ((x[2*nt+1] - mu) * rstd * sGam[col + 1] + sBet[col + 1]) * g1v;
            const __half h0 = __float2half_rn(y0), h1 = __float2half_rn(y1);
            const __half e0 = __float2half_rn(y0 - __half2float(h0));
            const __half e1 = __float2half_rn(y1 - __half2float(h1));
            *(uint32_t*)(oph + col) = packh2(h0, h1);
            *(uint32_t*)(opl + col) = packh2(e0, e1);
        }
    }
}

// ---------------- launch ---------------------------------------------------
extern "C" void kernel_launch(void* const* d_in, const int* in_sizes, int n_in,
                              void* d_out, int out_size) {
    const float* X     = (const float*)d_in[0];
    const int*   pos   = (const int*)d_in[1];
    const float* Wq    = (const float*)d_in[2];
    const float* Wk    = (const float*)d_in[3];
    const float* Wv    = (const float*)d_in[4];
    const float* Wo    = (const float*)d_in[5];
    const float* Wg1   = (const float*)d_in[6];
    const float* bg1   = (const float*)d_in[7];
    const float* Wg2   = (const float*)d_in[8];
    const float* bg2   = (const float*)d_in[9];
    const float* gamma = (const float*)d_in[10];
    const float* beta  = (const float*)d_in[11];
    float* out = (float*)d_out;

    void *pQ, *pK, *pV, *pG1, *pG2, *pRT;
    void *pXh, *pXl, *pOh, *pOl, *pWh, *pWl, *pWoh, *pWol;
    void *pQh, *pQl, *pKh, *pKl, *pVTh, *pVTl;
    cudaGetSymbolAddress(&pQ,  g_Q);
    cudaGetSymbolAddress(&pK,  g_K);
    cudaGetSymbolAddress(&pV,  g_V);
    cudaGetSymbolAddress(&pG1, g_G1);
    cudaGetSymbolAddress(&pG2, g_G2);
    cudaGetSymbolAddress(&pRT, g_RT);
    cudaGetSymbolAddress(&pXh, g_Xh);
    cudaGetSymbolAddress(&pXl, g_Xl);
    cudaGetSymbolAddress(&pOh, g_Oh);
    cudaGetSymbolAddress(&pOl, g_Ol);
    cudaGetSymbolAddress(&pWh, g_WqkvTh);
    cudaGetSymbolAddress(&pWl, g_WqkvTl);
    cudaGetSymbolAddress(&pWoh, g_WoTh);
    cudaGetSymbolAddress(&pWol, g_WoTl);
    cudaGetSymbolAddress(&pQh, g_Qh);
    cudaGetSymbolAddress(&pQl, g_Ql);
    cudaGetSymbolAddress(&pKh, g_Kh);
    cudaGetSymbolAddress(&pKl, g_Kl);
    cudaGetSymbolAddress(&pVTh, g_VTh);
    cudaGetSymbolAddress(&pVTl, g_VTl);

    float* Qp  = (float*)pQ;
    float* Kp  = (float*)pK;
    float* Vp  = (float*)pV;
    float* G1p = (float*)pG1;
    float* G2p = (float*)pG2;
    float* RTp = (float*)pRT;

    // prep
    split_kernel<<<512, 256>>>((const float4*)X, (uint2*)pXh, (uint2*)pXl,
                               TOK * HID / 4);
    rope_table<<<(S_LEN * 64 + 255) / 256, 256>>>(pos, RTp);
    wqkv_tsplit<<<dim3(HID / 32, NQKV / 32), dim3(32, 8)>>>(
        Wq, Wk, Wv, (__half*)pWh, (__half*)pWl);
    wo_tsplit<<<dim3(QDIM / 32, HID / 32), dim3(32, 8)>>>(
        Wo, (__half*)pWoh, (__half*)pWol);
    gates_kernel<<<TOK, 256>>>(X, Wg1, bg1, Wg2, bg2, G1p, G2p);

    // QKV projection (HMMA, 3-pass)
    cudaFuncSetAttribute(gemm_qkv_tc, cudaFuncAttributeMaxDynamicSharedMemorySize,
                         GEMM_SMEM);
    gemm_qkv_tc<<<dim3(NQKV / 128, TOK / 128), 256, GEMM_SMEM>>>(
        (const __half*)pXh, (const __half*)pXl,
        (const __half*)pWh, (const __half*)pWl, Qp, Kp, Vp);

    // fused RoPE + split for Q and K; transpose+split V
    rope_split<<<1024, 256>>>(Qp, RTp, (__half*)pQh, (__half*)pQl, NH);
    rope_split<<<256, 256>>>(Kp, RTp, (__half*)pKh, (__half*)pKl, NKV);
    vt_tsplit<<<dim3(KVDIM / 32, S_LEN / 32, BATCH), dim3(32, 8)>>>(
        Vp, (__half*)pVTh, (__half*)pVTl);

    // HMMA flash attention (2-pass split), double-buffered K/V
    cudaFuncSetAttribute(attn_hmma, cudaFuncAttributeMaxDynamicSharedMemorySize,
                         ATTN_SMEM);
    attn_hmma<<<dim3(S_LEN / BM, NH, BATCH), 256, ATTN_SMEM>>>(
        (const __half*)pQh,
        (const __half*)pKh, (const __half*)pKl,
        (const __half*)pVTh, (const __half*)pVTl,
        G1p, G2p, gamma, beta, (__half*)pOh, (__half*)pOl);

    // output projection (HMMA, 3-pass)
    cudaFuncSetAttribute(gemm_o_tc, cudaFuncAttributeMaxDynamicSharedMemorySize,
                         GEMM_SMEM);
    gemm_o_tc<<<dim3(HID / 128, TOK / 128), 256, GEMM_SMEM>>>(
        (const __half*)pOh, (const __half*)pOl,
        (const __half*)pWoh, (const __half*)pWol, out);
}